// round 3
// baseline (speedup 1.0000x reference)
#include <cuda_runtime.h>
#include <math.h>

#define BDIM 32
#define L1DIM 128
#define L2DIM 128
#define DDIM 300
#define KDIM 50
#define ROWS1 (BDIM * L1DIM)   // 4096
#define ROWS2 (BDIM * L2DIM)   // 4096
#define TSTRIDE (KDIM * DDIM)  // 15000

// Scratch (allocation-free rule: __device__ globals)
__device__ float g_t[(size_t)ROWS1 * TSTRIDE];   // 245.76 MB: t[b*i][k][e]
__device__ float g_p1d[ROWS1 * KDIM];
__device__ float g_p1g[ROWS1 * KDIM];
__device__ float g_p2d[ROWS2 * KDIM];
__device__ float g_p2g[ROWS2 * KDIM];

// Packed fp32x2 FMA (Blackwell FFMA2; PTX-only per sm_103a SASS quickref)
union f2u { float2 f; unsigned long long u; };
__device__ __forceinline__ float2 ffma2(float2 a, float2 b, float2 c) {
    f2u A, B, C, D;
    A.f = a; B.f = b; C.f = c;
    asm("fma.rn.f32x2 %0, %1, %2, %3;" : "=l"(D.u) : "l"(A.u), "l"(B.u), "l"(C.u));
    return D.f;
}

// ---------------------------------------------------------------------------
// Kernel 1: projections  p1d/p1g (from e1, Wd[:D]/Wg[:D]) and p2d/p2g
// (from e2, Wd[D:]/Wg[D:]).  Block = 32 rows of one source; W slices in smem.
// ---------------------------------------------------------------------------
#define P_ROWS 32
#define P_THREADS 256

__global__ void proj_kernel(const float* __restrict__ e1,
                            const float* __restrict__ e2,
                            const float* __restrict__ Wd,
                            const float* __restrict__ Wg) {
    extern __shared__ float sm[];
    float* rowsS = sm;                         // [32][300]
    float* WdS   = sm + P_ROWS * DDIM;         // [300][50]
    float* WgS   = WdS + DDIM * KDIM;          // [300][50]

    int blk  = blockIdx.x;
    bool s1  = (blk < (ROWS1 / P_ROWS));
    const float* E = s1 ? e1 : e2;
    int row0 = (s1 ? blk : blk - (ROWS1 / P_ROWS)) * P_ROWS;
    int woff = s1 ? 0 : DDIM * KDIM;           // Wd2/Wg2 start at row D
    float* outD = s1 ? g_p1d : g_p2d;
    float* outG = s1 ? g_p1g : g_p2g;
    int tid = threadIdx.x;

    const float4* Ef4 = reinterpret_cast<const float4*>(E + (size_t)row0 * DDIM);
    float4* rowsF4 = reinterpret_cast<float4*>(rowsS);
    for (int i = tid; i < P_ROWS * DDIM / 4; i += P_THREADS) rowsF4[i] = Ef4[i];

    const float4* Wd4 = reinterpret_cast<const float4*>(Wd + woff);
    const float4* Wg4 = reinterpret_cast<const float4*>(Wg + woff);
    float4* WdS4 = reinterpret_cast<float4*>(WdS);
    float4* WgS4 = reinterpret_cast<float4*>(WgS);
    for (int i = tid; i < DDIM * KDIM / 4; i += P_THREADS) {
        WdS4[i] = Wd4[i];
        WgS4[i] = Wg4[i];
    }
    __syncthreads();

    for (int o = tid; o < P_ROWS * KDIM; o += P_THREADS) {
        int r = o / KDIM, k = o % KDIM;
        const float* rr = rowsS + r * DDIM;
        float ad = 0.f, ag = 0.f;
        #pragma unroll 4
        for (int d = 0; d < DDIM; d++) {
            float x = rr[d];
            ad = fmaf(x, WdS[d * KDIM + k], ad);
            ag = fmaf(x, WgS[d * KDIM + k], ag);
        }
        outD[(row0 + r) * KDIM + k] = ad;
        outG[(row0 + r) * KDIM + k] = ag;
    }
}

// ---------------------------------------------------------------------------
// Kernel 2: t[m, k*300+e] = sum_d e1[m,d] * Wb[k,d,e]
// Per-k GEMM: A = e1 (4096x300), B = Wb[k] (300x300).
// Block tile 128x64, BK=16, 128 threads, 8x8 register tile, FFMA2 over n-pairs.
// ---------------------------------------------------------------------------
#define T_BM 128
#define T_BN 64
#define T_BK 16
#define T_THREADS 128
#define AS_LD 132   // padded (132 floats = 528B, 16B-aligned rows)

__global__ __launch_bounds__(T_THREADS)
void tmat_kernel(const float* __restrict__ e1, const float* __restrict__ Wb) {
    __shared__ float As[T_BK][AS_LD];
    __shared__ float Bs[T_BK][T_BN];

    int m0 = blockIdx.x * T_BM;
    int n0 = blockIdx.y * T_BN;
    int k  = blockIdx.z;
    const float* Bk = Wb + (size_t)k * DDIM * DDIM;

    int tid = threadIdx.x;
    int tn = tid & 7;    // 0..7  : n = n0 + 2*(tn + 8*p) + l
    int tm = tid >> 3;   // 0..15 : m = m0 + tm*8 + mm

    float2 acc[8][4];
    #pragma unroll
    for (int mm = 0; mm < 8; mm++)
        #pragma unroll
        for (int p = 0; p < 4; p++) acc[mm][p] = make_float2(0.f, 0.f);

    for (int d0 = 0; d0 < DDIM; d0 += T_BK) {
        // A tile: 128x16 = 512 float4, 4 per thread, store transposed As[d][m]
        #pragma unroll
        for (int it = 0; it < 4; it++) {
            int f4  = tid + T_THREADS * it;
            int row = f4 >> 2;          // 0..127
            int c4  = f4 & 3;           // 0..3
            int d   = d0 + c4 * 4;
            float4 v = make_float4(0.f, 0.f, 0.f, 0.f);
            if (d + 3 < DDIM)
                v = *reinterpret_cast<const float4*>(&e1[(size_t)(m0 + row) * DDIM + d]);
            As[c4 * 4 + 0][row] = v.x;
            As[c4 * 4 + 1][row] = v.y;
            As[c4 * 4 + 2][row] = v.z;
            As[c4 * 4 + 3][row] = v.w;
        }
        // B tile: 16x64 = 256 float4, 2 per thread
        #pragma unroll
        for (int it = 0; it < 2; it++) {
            int f4  = tid + T_THREADS * it;
            int row = f4 >> 4;          // 0..15
            int c4  = f4 & 15;          // 0..15
            int d   = d0 + row;
            int n   = n0 + c4 * 4;
            float4 v = make_float4(0.f, 0.f, 0.f, 0.f);
            if (d < DDIM && n < DDIM)   // n mult of 4, DDIM mult of 4
                v = *reinterpret_cast<const float4*>(&Bk[(size_t)d * DDIM + n]);
            *reinterpret_cast<float4*>(&Bs[row][c4 * 4]) = v;
        }
        __syncthreads();

        #pragma unroll
        for (int kk = 0; kk < T_BK; kk++) {
            float4 a0 = *reinterpret_cast<const float4*>(&As[kk][tm * 8]);
            float4 a1 = *reinterpret_cast<const float4*>(&As[kk][tm * 8 + 4]);
            float a[8] = {a0.x, a0.y, a0.z, a0.w, a1.x, a1.y, a1.z, a1.w};
            float2 b2[4];
            #pragma unroll
            for (int p = 0; p < 4; p++)
                b2[p] = *reinterpret_cast<const float2*>(&Bs[kk][2 * tn + 16 * p]);
            #pragma unroll
            for (int mm = 0; mm < 8; mm++)
                #pragma unroll
                for (int p = 0; p < 4; p++)
                    acc[mm][p] = ffma2(make_float2(a[mm], a[mm]), b2[p], acc[mm][p]);
        }
        __syncthreads();
    }

    // store t: row m, columns k*300 + n .. n+1
    #pragma unroll
    for (int mm = 0; mm < 8; mm++) {
        int m = m0 + tm * 8 + mm;
        float* crow = g_t + (size_t)m * TSTRIDE + k * DDIM;
        #pragma unroll
        for (int p = 0; p < 4; p++) {
            int n = n0 + 2 * tn + 16 * p;
            if (n < DDIM)
                *reinterpret_cast<float2*>(&crow[n]) = acc[mm][p];
        }
    }
}

// ---------------------------------------------------------------------------
// Kernel 3: per (b,i) block: btp[k][j] = sum_e t[m,k,e]*e2[b,j,e],
// fused gating + u-reduction -> out[b,i,j].
// 160 threads: tk = tid/16 (k = tk + 10*kk, kk<5), tj = tid%16 (j = 2*(tj+16*jj)+l).
// ---------------------------------------------------------------------------
#define F_THREADS 160
#define F_ECH 20
#define TS_LD 52

__global__ __launch_bounds__(F_THREADS)
void fuse_kernel(const float* __restrict__ e2,
                 const float* __restrict__ bg,
                 const float* __restrict__ bb,
                 const float* __restrict__ u,
                 float* __restrict__ out) {
    extern __shared__ float sm[];
    float* tS      = sm;                            // [20][52]   = 1040
    float* e2S     = tS + F_ECH * TS_LD;            // [20][128]  = 2560
    float* p2dS    = e2S + F_ECH * 128;             // [128][50]  = 6400
    float* p2gS    = p2dS + 128 * KDIM;             // 6400
    float* partial = p2gS + 128 * KDIM;             // [10][128]  = 1280
    float* p1dS    = partial + 10 * 128;            // 64-padded scalars
    float* p1gS    = p1dS + 64;
    float* uS      = p1gS + 64;
    float* bgS     = uS + 64;
    float* bbS     = bgS + 64;

    int blk = blockIdx.x;        // = b*128 + i
    int b   = blk >> 7;
    int m   = blk;
    int tid = threadIdx.x;
    int tj  = tid & 15;          // 0..15
    int tk  = tid >> 4;          // 0..9

    // preload per-block constants
    {
        const float4* p2d4 = reinterpret_cast<const float4*>(g_p2d + (size_t)b * 128 * KDIM);
        const float4* p2g4 = reinterpret_cast<const float4*>(g_p2g + (size_t)b * 128 * KDIM);
        float4* p2dS4 = reinterpret_cast<float4*>(p2dS);
        float4* p2gS4 = reinterpret_cast<float4*>(p2gS);
        for (int i = tid; i < 128 * KDIM / 4; i += F_THREADS) {
            p2dS4[i] = p2d4[i];
            p2gS4[i] = p2g4[i];
        }
        if (tid < KDIM) {
            p1dS[tid] = g_p1d[m * KDIM + tid];
            p1gS[tid] = g_p1g[m * KDIM + tid];
            uS[tid]   = u[tid];
            bgS[tid]  = bg[tid];
            bbS[tid]  = bb[tid];
        }
    }

    float2 acc[5][4];
    #pragma unroll
    for (int kk = 0; kk < 5; kk++)
        #pragma unroll
        for (int jj = 0; jj < 4; jj++) acc[kk][jj] = make_float2(0.f, 0.f);

    const float* trow = g_t + (size_t)m * TSTRIDE;
    const float* e2b  = e2 + (size_t)b * 128 * DDIM;

    for (int e0 = 0; e0 < DDIM; e0 += F_ECH) {
        __syncthreads();
        // tS: 50 k x 20 e = 250 float4 (5 per k), transposed to [e][k]
        for (int idx = tid; idx < KDIM * (F_ECH / 4); idx += F_THREADS) {
            int kq = idx / (F_ECH / 4);
            int q  = idx % (F_ECH / 4);
            float4 v = *reinterpret_cast<const float4*>(&trow[kq * DDIM + e0 + 4 * q]);
            tS[(4 * q + 0) * TS_LD + kq] = v.x;
            tS[(4 * q + 1) * TS_LD + kq] = v.y;
            tS[(4 * q + 2) * TS_LD + kq] = v.z;
            tS[(4 * q + 3) * TS_LD + kq] = v.w;
        }
        // e2S: 128 j x 20 e = 640 float4, transposed to [e][j]
        for (int idx = tid; idx < 128 * (F_ECH / 4); idx += F_THREADS) {
            int j = idx / (F_ECH / 4);
            int q = idx % (F_ECH / 4);
            float4 v = *reinterpret_cast<const float4*>(&e2b[j * DDIM + e0 + 4 * q]);
            e2S[(4 * q + 0) * 128 + j] = v.x;
            e2S[(4 * q + 1) * 128 + j] = v.y;
            e2S[(4 * q + 2) * 128 + j] = v.z;
            e2S[(4 * q + 3) * 128 + j] = v.w;
        }
        __syncthreads();

        #pragma unroll 4
        for (int e = 0; e < F_ECH; e++) {
            float a[5];
            #pragma unroll
            for (int kk = 0; kk < 5; kk++) a[kk] = tS[e * TS_LD + tk + 10 * kk];
            #pragma unroll
            for (int jj = 0; jj < 4; jj++) {
                float2 bv = *reinterpret_cast<const float2*>(&e2S[e * 128 + 2 * (tj + 16 * jj)]);
                #pragma unroll
                for (int kk = 0; kk < 5; kk++)
                    acc[kk][jj] = ffma2(make_float2(a[kk], a[kk]), bv, acc[kk][jj]);
            }
        }
    }
    __syncthreads();

    // epilogue: gating + u-weighted partial sums over this thread's 5 k's
    float pj[4][2];
    #pragma unroll
    for (int jj = 0; jj < 4; jj++) { pj[jj][0] = 0.f; pj[jj][1] = 0.f; }

    #pragma unroll
    for (int kk = 0; kk < 5; kk++) {
        int k = tk + 10 * kk;
        float p1d = p1dS[k], p1g = p1gS[k];
        float bgk = bgS[k], uk = uS[k], bk = bbS[k];
        #pragma unroll
        for (int jj = 0; jj < 4; jj++) {
            int j0 = 2 * (tj + 16 * jj);
            #pragma unroll
            for (int l = 0; l < 2; l++) {
                int j = j0 + l;
                float btp = l ? acc[kk][jj].y : acc[kk][jj].x;
                float sd  = p1d + p2dS[j * KDIM + k];
                float sg  = p1g + p2gS[j * KDIM + k] + bgk;
                float g   = 1.0f / (1.0f + __expf(-sg));
                float sln = tanhf(sd);
                float mix = fmaf(g, btp - sln, sln) + bk;   // g*btp + (1-g)*sln + bk
                pj[jj][l] = fmaf(uk, mix, pj[jj][l]);
            }
        }
    }

    #pragma unroll
    for (int jj = 0; jj < 4; jj++) {
        int j0 = 2 * (tj + 16 * jj);
        partial[tk * 128 + j0]     = pj[jj][0];
        partial[tk * 128 + j0 + 1] = pj[jj][1];
    }
    __syncthreads();

    if (tid < 128) {
        float s = 0.f;
        #pragma unroll
        for (int t = 0; t < 10; t++) s += partial[t * 128 + tid];
        out[(size_t)blk * 128 + tid] = s;
    }
}

// ---------------------------------------------------------------------------
extern "C" void kernel_launch(void* const* d_in, const int* in_sizes, int n_in,
                              void* d_out, int out_size) {
    const float* e1 = (const float*)d_in[0];
    const float* e2 = (const float*)d_in[1];
    const float* Wb = (const float*)d_in[2];
    const float* Wd = (const float*)d_in[3];
    const float* Wg = (const float*)d_in[4];
    const float* bg = (const float*)d_in[5];
    const float* bb = (const float*)d_in[6];
    const float* u  = (const float*)d_in[7];
    float* out = (float*)d_out;

    constexpr int P_SMEM = (P_ROWS * DDIM + 2 * DDIM * KDIM) * sizeof(float);           // 158.4 KB
    constexpr int F_SMEM = (F_ECH * TS_LD + F_ECH * 128 + 2 * 128 * KDIM + 10 * 128 + 5 * 64) * sizeof(float); // ~72 KB

    cudaFuncSetAttribute(proj_kernel, cudaFuncAttributeMaxDynamicSharedMemorySize, P_SMEM);
    cudaFuncSetAttribute(fuse_kernel, cudaFuncAttributeMaxDynamicSharedMemorySize, F_SMEM);

    proj_kernel<<<2 * (ROWS1 / P_ROWS), P_THREADS, P_SMEM>>>(e1, e2, Wd, Wg);
    tmat_kernel<<<dim3(ROWS1 / T_BM, (DDIM + T_BN - 1) / T_BN, KDIM), T_THREADS>>>(e1, Wb);
    fuse_kernel<<<ROWS1, F_THREADS, F_SMEM>>>(e2, bg, bb, u, out);
}

// round 4
// speedup vs baseline: 1.1389x; 1.1389x over previous
#include <cuda_runtime.h>
#include <math.h>

#define BDIM 32
#define L1DIM 128
#define L2DIM 128
#define DDIM 300
#define KDIM 50
#define ROWS1 (BDIM * L1DIM)   // 4096
#define ROWS2 (BDIM * L2DIM)   // 4096
#define TSTRIDE (KDIM * DDIM)  // 15000

// Scratch (allocation-free rule: __device__ globals)
__device__ float g_t[(size_t)ROWS1 * TSTRIDE];   // 245.76 MB: t[b*i][k][e]
__device__ float g_p1d[ROWS1 * KDIM];
__device__ float g_p1g[ROWS1 * KDIM];
__device__ float g_p2d[ROWS2 * KDIM];
__device__ float g_p2g[ROWS2 * KDIM];

// Packed fp32x2 FMA (Blackwell FFMA2; PTX-only)
union f2u { float2 f; unsigned long long u; };
__device__ __forceinline__ float2 ffma2(float2 a, float2 b, float2 c) {
    f2u A, B, C, D;
    A.f = a; B.f = b; C.f = c;
    asm("fma.rn.f32x2 %0, %1, %2, %3;" : "=l"(D.u) : "l"(A.u), "l"(B.u), "l"(C.u));
    return D.f;
}

// ---------------------------------------------------------------------------
// Kernel 1: projections. Grid 512: blk -> (row-tile of 32, mat in {d,g},
// side in {e1,e2}). One W slice (300x50 = 60KB) in smem; rows transposed
// [d][r] with pad 33 (conflict-free). Thread = (r, k0); 7 k's per row-load.
// ---------------------------------------------------------------------------
#define P_ROWS 32
#define P_THREADS 256
#define P_RPAD 33

__global__ __launch_bounds__(P_THREADS)
void proj_kernel(const float* __restrict__ e1,
                 const float* __restrict__ e2,
                 const float* __restrict__ Wd,
                 const float* __restrict__ Wg) {
    extern __shared__ float sm[];
    float* WS   = sm;                    // [300][50]
    float* rowS = sm + DDIM * KDIM;      // [300][33] (transposed rows)

    int blk = blockIdx.x;
    int rt  = blk & 127;                 // row tile
    int mt  = (blk >> 7) & 1;            // 0 = d-proj, 1 = g-proj
    int s   = blk >> 8;                  // 0 = e1 side, 1 = e2 side
    int row0 = rt * P_ROWS;
    int tid = threadIdx.x;

    const float* E = s ? e2 : e1;
    const float* W = (mt ? Wg : Wd) + s * DDIM * KDIM;
    float* out = s ? (mt ? g_p2g : g_p2d) : (mt ? g_p1g : g_p1d);

    // stage W (3750 float4)
    const float4* W4 = reinterpret_cast<const float4*>(W);
    float4* WS4 = reinterpret_cast<float4*>(WS);
    for (int i = tid; i < DDIM * KDIM / 4; i += P_THREADS) WS4[i] = W4[i];

    // stage rows transposed: rowS[d][r]
    for (int i = tid; i < P_ROWS * (DDIM / 4); i += P_THREADS) {
        int r = i / (DDIM / 4);
        int c4 = i % (DDIM / 4);
        float4 v = *reinterpret_cast<const float4*>(&E[(size_t)(row0 + r) * DDIM + 4 * c4]);
        rowS[(4 * c4 + 0) * P_RPAD + r] = v.x;
        rowS[(4 * c4 + 1) * P_RPAD + r] = v.y;
        rowS[(4 * c4 + 2) * P_RPAD + r] = v.z;
        rowS[(4 * c4 + 3) * P_RPAD + r] = v.w;
    }
    __syncthreads();

    int r  = tid & 31;
    int k0 = tid >> 5;                   // 0..7
    float acc[7];
    #pragma unroll
    for (int t = 0; t < 7; t++) acc[t] = 0.f;

    #pragma unroll 4
    for (int d = 0; d < DDIM; d++) {
        float x = rowS[d * P_RPAD + r];
        const float* wrow = &WS[d * KDIM + k0];
        #pragma unroll
        for (int t = 0; t < 7; t++)
            acc[t] = fmaf(x, wrow[8 * t], acc[t]);   // may over-read into rowS; guarded at store
    }

    #pragma unroll
    for (int t = 0; t < 7; t++) {
        int k = k0 + 8 * t;
        if (k < KDIM) out[(size_t)(row0 + r) * KDIM + k] = acc[t];
    }
}

// ---------------------------------------------------------------------------
// Kernel 2: t[m, k*300+e] = sum_d e1[m,d] * Wb[k,d,e]
// 128x64 block tile, BK=16, 128 threads, 8x8 reg tile, FFMA2,
// double-buffered smem with LDG->reg->STS pipeline (1 sync / iter).
// ---------------------------------------------------------------------------
#define T_BM 128
#define T_BN 64
#define T_BK 16
#define T_THREADS 128
#define AS_LD 132
#define T_NIT ((DDIM + T_BK - 1) / T_BK)   // 19

__global__ __launch_bounds__(T_THREADS)
void tmat_kernel(const float* __restrict__ e1, const float* __restrict__ Wb) {
    __shared__ float As[2][T_BK][AS_LD];
    __shared__ float Bs[2][T_BK][T_BN];

    int m0 = blockIdx.x * T_BM;
    int n0 = blockIdx.y * T_BN;
    int k  = blockIdx.z;
    const float* Bk = Wb + (size_t)k * DDIM * DDIM;

    int tid = threadIdx.x;
    int tn = tid & 7;
    int tm = tid >> 3;

    float2 acc[8][4];
    #pragma unroll
    for (int mm = 0; mm < 8; mm++)
        #pragma unroll
        for (int p = 0; p < 4; p++) acc[mm][p] = make_float2(0.f, 0.f);

    float4 rA[4], rB[2];

    auto ldg_tile = [&](int d0) {
        #pragma unroll
        for (int it = 0; it < 4; it++) {
            int f4  = tid + T_THREADS * it;
            int row = f4 >> 2;
            int c4  = f4 & 3;
            int d   = d0 + c4 * 4;
            rA[it] = (d + 4 <= DDIM)
                ? *reinterpret_cast<const float4*>(&e1[(size_t)(m0 + row) * DDIM + d])
                : make_float4(0.f, 0.f, 0.f, 0.f);
        }
        #pragma unroll
        for (int it = 0; it < 2; it++) {
            int f4  = tid + T_THREADS * it;
            int row = f4 >> 4;
            int c4  = f4 & 15;
            int d   = d0 + row;
            int n   = n0 + c4 * 4;
            rB[it] = (d < DDIM && n < DDIM)
                ? *reinterpret_cast<const float4*>(&Bk[(size_t)d * DDIM + n])
                : make_float4(0.f, 0.f, 0.f, 0.f);
        }
    };

    auto sts_tile = [&](int bsel) {
        #pragma unroll
        for (int it = 0; it < 4; it++) {
            int f4  = tid + T_THREADS * it;
            int row = f4 >> 2;
            int c4  = f4 & 3;
            As[bsel][c4 * 4 + 0][row] = rA[it].x;
            As[bsel][c4 * 4 + 1][row] = rA[it].y;
            As[bsel][c4 * 4 + 2][row] = rA[it].z;
            As[bsel][c4 * 4 + 3][row] = rA[it].w;
        }
        #pragma unroll
        for (int it = 0; it < 2; it++) {
            int f4  = tid + T_THREADS * it;
            int row = f4 >> 4;
            int c4  = f4 & 15;
            *reinterpret_cast<float4*>(&Bs[bsel][row][c4 * 4]) = rB[it];
        }
    };

    ldg_tile(0);
    sts_tile(0);
    __syncthreads();

    for (int i = 0; i < T_NIT; i++) {
        if (i + 1 < T_NIT) ldg_tile((i + 1) * T_BK);
        int cur = i & 1;
        #pragma unroll
        for (int kk = 0; kk < T_BK; kk++) {
            float4 a0 = *reinterpret_cast<const float4*>(&As[cur][kk][tm * 8]);
            float4 a1 = *reinterpret_cast<const float4*>(&As[cur][kk][tm * 8 + 4]);
            float a[8] = {a0.x, a0.y, a0.z, a0.w, a1.x, a1.y, a1.z, a1.w};
            float2 b2[4];
            #pragma unroll
            for (int p = 0; p < 4; p++)
                b2[p] = *reinterpret_cast<const float2*>(&Bs[cur][kk][2 * tn + 16 * p]);
            #pragma unroll
            for (int mm = 0; mm < 8; mm++)
                #pragma unroll
                for (int p = 0; p < 4; p++)
                    acc[mm][p] = ffma2(make_float2(a[mm], a[mm]), b2[p], acc[mm][p]);
        }
        if (i + 1 < T_NIT) sts_tile((i + 1) & 1);
        __syncthreads();
    }

    #pragma unroll
    for (int mm = 0; mm < 8; mm++) {
        int m = m0 + tm * 8 + mm;
        float* crow = g_t + (size_t)m * TSTRIDE + k * DDIM;
        #pragma unroll
        for (int p = 0; p < 4; p++) {
            int n = n0 + 2 * tn + 16 * p;
            if (n < DDIM)
                *reinterpret_cast<float2*>(&crow[n]) = acc[mm][p];
        }
    }
}

// ---------------------------------------------------------------------------
// Kernel 3: per (b,i): btp[k][j] = sum_e t[m,k,e]*e2[b,j,e], fused gating +
// u-reduction. Double-buffered e-chunks; p2d/p2g read from L2 in epilogue.
// ---------------------------------------------------------------------------
#define F_THREADS 160
#define F_ECH 20
#define TS_LD 52
#define F_NIT (DDIM / F_ECH)     // 15

__global__ __launch_bounds__(F_THREADS)
void fuse_kernel(const float* __restrict__ e2,
                 const float* __restrict__ bg,
                 const float* __restrict__ bb,
                 const float* __restrict__ u,
                 float* __restrict__ out) {
    __shared__ float tS[2][F_ECH][TS_LD];
    __shared__ float e2S[2][F_ECH][128];
    __shared__ float partial[10][128];
    __shared__ float p1dS[64], p1gS[64], uS[64], bgS[64], bbS[64];

    int blk = blockIdx.x;        // = b*128 + i
    int b   = blk >> 7;
    int m   = blk;
    int tid = threadIdx.x;
    int tj  = tid & 15;
    int tk  = tid >> 4;

    const float* trow   = g_t + (size_t)m * TSTRIDE;
    const float* e2b    = e2 + (size_t)b * 128 * DDIM;
    const float* p2drow = g_p2d + (size_t)b * 128 * KDIM;
    const float* p2grow = g_p2g + (size_t)b * 128 * KDIM;

    if (tid < KDIM) {
        p1dS[tid] = g_p1d[m * KDIM + tid];
        p1gS[tid] = g_p1g[m * KDIM + tid];
        uS[tid]   = u[tid];
        bgS[tid]  = bg[tid];
        bbS[tid]  = bb[tid];
    }

    // staging registers: tS needs 250 float4 (threads 0..89 carry 2),
    // e2S needs 640 float4 (exactly 4 per thread)
    float4 rT0, rT1, rE[4];
    bool t1v = (tid + F_THREADS) < KDIM * (F_ECH / 4);

    auto ldg_chunk = [&](int e0) {
        {
            int idx = tid; int kq = idx / 5, q = idx - kq * 5;
            rT0 = *reinterpret_cast<const float4*>(&trow[kq * DDIM + e0 + 4 * q]);
        }
        if (t1v) {
            int idx = tid + F_THREADS; int kq = idx / 5, q = idx - kq * 5;
            rT1 = *reinterpret_cast<const float4*>(&trow[kq * DDIM + e0 + 4 * q]);
        }
        #pragma unroll
        for (int it = 0; it < 4; it++) {
            int idx = tid + F_THREADS * it; int j = idx / 5, q = idx - j * 5;
            rE[it] = *reinterpret_cast<const float4*>(&e2b[j * DDIM + e0 + 4 * q]);
        }
    };

    auto sts_chunk = [&](int bsel) {
        {
            int idx = tid; int kq = idx / 5, q = idx - kq * 5;
            tS[bsel][4 * q + 0][kq] = rT0.x;
            tS[bsel][4 * q + 1][kq] = rT0.y;
            tS[bsel][4 * q + 2][kq] = rT0.z;
            tS[bsel][4 * q + 3][kq] = rT0.w;
        }
        if (t1v) {
            int idx = tid + F_THREADS; int kq = idx / 5, q = idx - kq * 5;
            tS[bsel][4 * q + 0][kq] = rT1.x;
            tS[bsel][4 * q + 1][kq] = rT1.y;
            tS[bsel][4 * q + 2][kq] = rT1.z;
            tS[bsel][4 * q + 3][kq] = rT1.w;
        }
        #pragma unroll
        for (int it = 0; it < 4; it++) {
            int idx = tid + F_THREADS * it; int j = idx / 5, q = idx - j * 5;
            e2S[bsel][4 * q + 0][j] = rE[it].x;
            e2S[bsel][4 * q + 1][j] = rE[it].y;
            e2S[bsel][4 * q + 2][j] = rE[it].z;
            e2S[bsel][4 * q + 3][j] = rE[it].w;
        }
    };

    float2 acc[5][4];
    #pragma unroll
    for (int kk = 0; kk < 5; kk++)
        #pragma unroll
        for (int jj = 0; jj < 4; jj++) acc[kk][jj] = make_float2(0.f, 0.f);

    ldg_chunk(0);
    sts_chunk(0);
    __syncthreads();

    for (int i = 0; i < F_NIT; i++) {
        if (i + 1 < F_NIT) ldg_chunk((i + 1) * F_ECH);
        int cur = i & 1;
        #pragma unroll 4
        for (int e = 0; e < F_ECH; e++) {
            float a[5];
            #pragma unroll
            for (int kk = 0; kk < 5; kk++) a[kk] = tS[cur][e][tk + 10 * kk];
            #pragma unroll
            for (int jj = 0; jj < 4; jj++) {
                float2 bv = *reinterpret_cast<const float2*>(&e2S[cur][e][2 * (tj + 16 * jj)]);
                #pragma unroll
                for (int kk = 0; kk < 5; kk++)
                    acc[kk][jj] = ffma2(make_float2(a[kk], a[kk]), bv, acc[kk][jj]);
            }
        }
        if (i + 1 < F_NIT) sts_chunk((i + 1) & 1);
        __syncthreads();
    }

    // epilogue: gating + u-weighted partials; p2d/p2g straight from L2
    float pj[4][2];
    #pragma unroll
    for (int jj = 0; jj < 4; jj++) { pj[jj][0] = 0.f; pj[jj][1] = 0.f; }

    #pragma unroll
    for (int kk = 0; kk < 5; kk++) {
        int k = tk + 10 * kk;
        float p1d = p1dS[k], p1g = p1gS[k];
        float bgk = bgS[k], uk = uS[k], bk = bbS[k];
        #pragma unroll
        for (int jj = 0; jj < 4; jj++) {
            int j0 = 2 * (tj + 16 * jj);
            #pragma unroll
            for (int l = 0; l < 2; l++) {
                int j = j0 + l;
                float btp = l ? acc[kk][jj].y : acc[kk][jj].x;
                float sd  = p1d + __ldg(&p2drow[j * KDIM + k]);
                float sg  = p1g + __ldg(&p2grow[j * KDIM + k]) + bgk;
                float g   = 1.0f / (1.0f + __expf(-sg));
                float sln = tanhf(sd);
                float mix = fmaf(g, btp - sln, sln) + bk;
                pj[jj][l] = fmaf(uk, mix, pj[jj][l]);
            }
        }
    }

    #pragma unroll
    for (int jj = 0; jj < 4; jj++) {
        int j0 = 2 * (tj + 16 * jj);
        partial[tk][j0]     = pj[jj][0];
        partial[tk][j0 + 1] = pj[jj][1];
    }
    __syncthreads();

    if (tid < 128) {
        float s = 0.f;
        #pragma unroll
        for (int t = 0; t < 10; t++) s += partial[t][tid];
        out[(size_t)blk * 128 + tid] = s;
    }
}

// ---------------------------------------------------------------------------
extern "C" void kernel_launch(void* const* d_in, const int* in_sizes, int n_in,
                              void* d_out, int out_size) {
    const float* e1 = (const float*)d_in[0];
    const float* e2 = (const float*)d_in[1];
    const float* Wb = (const float*)d_in[2];
    const float* Wd = (const float*)d_in[3];
    const float* Wg = (const float*)d_in[4];
    const float* bg = (const float*)d_in[5];
    const float* bb = (const float*)d_in[6];
    const float* u  = (const float*)d_in[7];
    float* out = (float*)d_out;

    constexpr int P_SMEM = (DDIM * KDIM + DDIM * P_RPAD) * sizeof(float);  // 99.6 KB
    cudaFuncSetAttribute(proj_kernel, cudaFuncAttributeMaxDynamicSharedMemorySize, P_SMEM);

    proj_kernel<<<512, P_THREADS, P_SMEM>>>(e1, e2, Wd, Wg);
    tmat_kernel<<<dim3(ROWS1 / T_BM, (DDIM + T_BN - 1) / T_BN, KDIM), T_THREADS>>>(e1, Wb);
    fuse_kernel<<<ROWS1, F_THREADS>>>(e2, bg, bb, u, out);
}

// round 6
// speedup vs baseline: 1.6509x; 1.4495x over previous
#include <cuda_runtime.h>
#include <cuda_bf16.h>
#include <math.h>
#include <stdint.h>

#define BDIM 32
#define L1DIM 128
#define L2DIM 128
#define DDIM 300
#define KDIM 50
#define ROWS1 (BDIM * L1DIM)   // 4096
#define ROWS2 (BDIM * L2DIM)   // 4096
#define TSTRIDE (KDIM * DDIM)  // 15000
#define KPAD 320               // D padded: 5 chunks of 64 bf16
#define NPAD 15104             // 118 * 128 (n-tile padded rows for Wb')

// Scratch (allocation-free rule: __device__ globals; zero-initialized at load)
__device__ float g_t[(size_t)ROWS1 * TSTRIDE];           // 245.76 MB
__device__ float g_p1d[ROWS1 * KDIM];
__device__ float g_p1g[ROWS1 * KDIM];
__device__ float g_p2d[ROWS2 * KDIM];
__device__ float g_p2g[ROWS2 * KDIM];
__device__ __nv_bfloat16 g_e1h[(size_t)ROWS1 * KPAD];
__device__ __nv_bfloat16 g_e1l[(size_t)ROWS1 * KPAD];
__device__ __nv_bfloat16 g_wbh[(size_t)NPAD * KPAD];     // Wb'[(k,e)][d] hi
__device__ __nv_bfloat16 g_wbl[(size_t)NPAD * KPAD];     // lo

// ---------------------------------------------------------------------------
// helpers (all plain sm_80+ PTX — no arch-feature-gated instructions)
// ---------------------------------------------------------------------------
union f2u { float2 f; unsigned long long u; };
__device__ __forceinline__ float2 ffma2(float2 a, float2 b, float2 c) {
    f2u A, B, C, D;
    A.f = a; B.f = b; C.f = c;
    asm("fma.rn.f32x2 %0, %1, %2, %3;" : "=l"(D.u) : "l"(A.u), "l"(B.u), "l"(C.u));
    return D.f;
}
__device__ __forceinline__ uint32_t smem_u32(const void* p) {
    uint32_t a;
    asm("{ .reg .u64 t; cvta.to.shared.u64 t, %1; cvt.u32.u64 %0, t; }" : "=r"(a) : "l"(p));
    return a;
}
__device__ __forceinline__ void cpasync16(uint32_t dst, const void* src) {
    asm volatile("cp.async.cg.shared.global [%0], [%1], 16;" :: "r"(dst), "l"(src));
}
__device__ __forceinline__ void ldsm_x4(uint32_t& r0, uint32_t& r1, uint32_t& r2,
                                        uint32_t& r3, uint32_t addr) {
    asm volatile("ldmatrix.sync.aligned.m8n8.x4.shared.b16 {%0,%1,%2,%3}, [%4];"
                 : "=r"(r0), "=r"(r1), "=r"(r2), "=r"(r3) : "r"(addr));
}
__device__ __forceinline__ void mma_bf16(float* c, const uint32_t* a, const uint32_t* b) {
    asm volatile(
        "mma.sync.aligned.m16n8k16.row.col.f32.bf16.bf16.f32 "
        "{%0,%1,%2,%3}, {%4,%5,%6,%7}, {%8,%9}, {%0,%1,%2,%3};"
        : "+f"(c[0]), "+f"(c[1]), "+f"(c[2]), "+f"(c[3])
        : "r"(a[0]), "r"(a[1]), "r"(a[2]), "r"(a[3]), "r"(b[0]), "r"(b[1]));
}

// ---------------------------------------------------------------------------
// conversion kernels: fp32 -> bf16 hi/lo split (padded with zeros)
// ---------------------------------------------------------------------------
__global__ void convA_kernel(const float* __restrict__ e1) {
    int m = blockIdx.x;
    int d = threadIdx.x;                 // 0..319
    float v = (d < DDIM) ? e1[(size_t)m * DDIM + d] : 0.f;
    __nv_bfloat16 hi = __float2bfloat16(v);
    __nv_bfloat16 lo = __float2bfloat16(v - __bfloat162float(hi));
    g_e1h[(size_t)m * KPAD + d] = hi;
    g_e1l[(size_t)m * KPAD + d] = lo;
}

// Wb[k][d][e] -> Wb'[(k*300+e)][d] (transposed per k, padded, split)
__global__ void convB_kernel(const float* __restrict__ Wb) {
    __shared__ float tile[32][33];
    int k  = blockIdx.z;
    int d0 = blockIdx.x * 32;
    int e0 = blockIdx.y * 32;
    int tx = threadIdx.x, ty = threadIdx.y;   // 32 x 8
    #pragma unroll
    for (int q = 0; q < 4; q++) {
        int d = d0 + ty + 8 * q;
        int e = e0 + tx;
        float v = 0.f;
        if (d < DDIM && e < DDIM)
            v = Wb[(size_t)k * DDIM * DDIM + (size_t)d * DDIM + e];
        tile[ty + 8 * q][tx] = v;
    }
    __syncthreads();
    #pragma unroll
    for (int q = 0; q < 4; q++) {
        int e = e0 + ty + 8 * q;
        int d = d0 + tx;
        if (e < DDIM) {
            float v = tile[tx][ty + 8 * q];
            __nv_bfloat16 hi = __float2bfloat16(v);
            __nv_bfloat16 lo = __float2bfloat16(v - __bfloat162float(hi));
            size_t o = (size_t)(k * DDIM + e) * KPAD + d;
            g_wbh[o] = hi;
            g_wbl[o] = lo;
        }
    }
}

// ---------------------------------------------------------------------------
// Stage-1 GEMM on tensor cores (mma.sync bf16, 3-pass hi/lo split):
//   g_t[4096 x 15000] = e1[4096 x 320] @ Wb'[15104 x 320]^T
// CTA tile 128x128, 8 warps (warp 32x64), k-chunks of 64, cp.async 2-stage.
// ---------------------------------------------------------------------------
#define MM_THREADS 256
#define MM_KC 64
#define MM_LDS 72                         // bf16/row: 64 data + 8 pad
#define MM_ROWB (MM_LDS * 2)              // 144 B row stride
#define ATILE_B (128 * MM_ROWB)           // 18432 B per matrix
#define STAGE_B (4 * ATILE_B)             // Ah, Al, Bh, Bl
#define MM_SMEM (2 * STAGE_B)             // 147456 B
#define NCHUNK (KPAD / MM_KC)             // 5

__global__ __launch_bounds__(MM_THREADS, 1)
void tmat_mma_kernel() {
    extern __shared__ char smem[];
    uint32_t sb = smem_u32(smem);
    int tid  = threadIdx.x;
    int lane = tid & 31;
    int w    = tid >> 5;
    int wm   = (w >> 1) * 32;             // warp m offset in tile
    int wn   = (w & 1) * 64;              // warp n offset in tile
    int m0 = blockIdx.x * 128;
    int n0 = blockIdx.y * 128;

    float acc[2][8][4];
    #pragma unroll
    for (int mt = 0; mt < 2; mt++)
        #pragma unroll
        for (int nt = 0; nt < 8; nt++)
            #pragma unroll
            for (int q = 0; q < 4; q++) acc[mt][nt][q] = 0.f;

    auto issue = [&](int c) {
        int d0 = c * MM_KC;
        uint32_t stage = sb + (c & 1) * STAGE_B;
        #pragma unroll
        for (int it = 0; it < 16; it++) {
            int i = tid + MM_THREADS * it;
            int mat = i >> 10;
            int idx = i & 1023;
            int r = idx >> 3, c4 = idx & 7;
            const __nv_bfloat16* src;
            if (mat == 0)      src = &g_e1h[(size_t)(m0 + r) * KPAD + d0 + c4 * 8];
            else if (mat == 1) src = &g_e1l[(size_t)(m0 + r) * KPAD + d0 + c4 * 8];
            else if (mat == 2) src = &g_wbh[(size_t)(n0 + r) * KPAD + d0 + c4 * 8];
            else               src = &g_wbl[(size_t)(n0 + r) * KPAD + d0 + c4 * 8];
            cpasync16(stage + mat * ATILE_B + r * MM_ROWB + c4 * 16, src);
        }
        asm volatile("cp.async.commit_group;" ::: "memory");
    };

    issue(0);

    for (int c = 0; c < NCHUNK; c++) {
        if (c + 1 < NCHUNK) {
            issue(c + 1);
            asm volatile("cp.async.wait_group 1;" ::: "memory");
        } else {
            asm volatile("cp.async.wait_group 0;" ::: "memory");
        }
        __syncthreads();

        uint32_t sA_h = sb + (c & 1) * STAGE_B;
        uint32_t sA_l = sA_h + ATILE_B;
        uint32_t sB_h = sA_h + 2 * ATILE_B;
        uint32_t sB_l = sA_h + 3 * ATILE_B;

        #pragma unroll
        for (int kk = 0; kk < MM_KC / 16; kk++) {
            uint32_t ah[2][4], al[2][4];
            #pragma unroll
            for (int mt = 0; mt < 2; mt++) {
                uint32_t aoff = (uint32_t)(wm + mt * 16 + (lane & 15)) * MM_ROWB
                              + kk * 32 + (lane >> 4) * 16;
                ldsm_x4(ah[mt][0], ah[mt][1], ah[mt][2], ah[mt][3], sA_h + aoff);
                ldsm_x4(al[mt][0], al[mt][1], al[mt][2], al[mt][3], sA_l + aoff);
            }
            uint32_t bh[8][2], bl[8][2];
            #pragma unroll
            for (int nq = 0; nq < 4; nq++) {
                uint32_t brow = (uint32_t)(wn + nq * 16 + (lane & 7) + ((lane >> 4) << 3));
                uint32_t boff = brow * MM_ROWB + kk * 32 + ((lane >> 3) & 1) * 16;
                ldsm_x4(bh[2*nq][0], bh[2*nq][1], bh[2*nq+1][0], bh[2*nq+1][1], sB_h + boff);
                ldsm_x4(bl[2*nq][0], bl[2*nq][1], bl[2*nq+1][0], bl[2*nq+1][1], sB_l + boff);
            }
            #pragma unroll
            for (int mt = 0; mt < 2; mt++)
                #pragma unroll
                for (int nt = 0; nt < 8; nt++) {
                    mma_bf16(acc[mt][nt], ah[mt], bh[nt]);   // hi*hi
                    mma_bf16(acc[mt][nt], ah[mt], bl[nt]);   // hi*lo
                    mma_bf16(acc[mt][nt], al[mt], bh[nt]);   // lo*hi
                }
        }
        __syncthreads();
    }

    // epilogue: fragment -> g_t (predicated on n < 15000)
    #pragma unroll
    for (int mt = 0; mt < 2; mt++) {
        int row = m0 + wm + mt * 16 + (lane >> 2);
        float* r0p = g_t + (size_t)row * TSTRIDE;
        float* r1p = r0p + (size_t)8 * TSTRIDE;
        #pragma unroll
        for (int nt = 0; nt < 8; nt++) {
            int col = n0 + wn + nt * 8 + 2 * (lane & 3);
            if (col < TSTRIDE) {
                *reinterpret_cast<float2*>(r0p + col) = make_float2(acc[mt][nt][0], acc[mt][nt][1]);
                *reinterpret_cast<float2*>(r1p + col) = make_float2(acc[mt][nt][2], acc[mt][nt][3]);
            }
        }
    }
}

// ---------------------------------------------------------------------------
// Kernel: projections (unchanged)
// ---------------------------------------------------------------------------
#define P_ROWS 32
#define P_THREADS 256
#define P_RPAD 33

__global__ __launch_bounds__(P_THREADS)
void proj_kernel(const float* __restrict__ e1,
                 const float* __restrict__ e2,
                 const float* __restrict__ Wd,
                 const float* __restrict__ Wg) {
    extern __shared__ float sm[];
    float* WS   = sm;
    float* rowS = sm + DDIM * KDIM;

    int blk = blockIdx.x;
    int rt  = blk & 127;
    int mt  = (blk >> 7) & 1;
    int s   = blk >> 8;
    int row0 = rt * P_ROWS;
    int tid = threadIdx.x;

    const float* E = s ? e2 : e1;
    const float* W = (mt ? Wg : Wd) + s * DDIM * KDIM;
    float* out = s ? (mt ? g_p2g : g_p2d) : (mt ? g_p1g : g_p1d);

    const float4* W4 = reinterpret_cast<const float4*>(W);
    float4* WS4 = reinterpret_cast<float4*>(WS);
    for (int i = tid; i < DDIM * KDIM / 4; i += P_THREADS) WS4[i] = W4[i];

    for (int i = tid; i < P_ROWS * (DDIM / 4); i += P_THREADS) {
        int r = i / (DDIM / 4);
        int c4 = i % (DDIM / 4);
        float4 v = *reinterpret_cast<const float4*>(&E[(size_t)(row0 + r) * DDIM + 4 * c4]);
        rowS[(4 * c4 + 0) * P_RPAD + r] = v.x;
        rowS[(4 * c4 + 1) * P_RPAD + r] = v.y;
        rowS[(4 * c4 + 2) * P_RPAD + r] = v.z;
        rowS[(4 * c4 + 3) * P_RPAD + r] = v.w;
    }
    __syncthreads();

    int r  = tid & 31;
    int k0 = tid >> 5;
    float acc[7];
    #pragma unroll
    for (int t = 0; t < 7; t++) acc[t] = 0.f;

    #pragma unroll 4
    for (int d = 0; d < DDIM; d++) {
        float x = rowS[d * P_RPAD + r];
        const float* wrow = &WS[d * KDIM + k0];
        #pragma unroll
        for (int t = 0; t < 7; t++)
            acc[t] = fmaf(x, wrow[8 * t], acc[t]);
    }

    #pragma unroll
    for (int t = 0; t < 7; t++) {
        int k = k0 + 8 * t;
        if (k < KDIM) out[(size_t)(row0 + r) * KDIM + k] = acc[t];
    }
}

// ---------------------------------------------------------------------------
// Kernel: fuse (unchanged)
// ---------------------------------------------------------------------------
#define F_THREADS 160
#define F_ECH 20
#define TS_LD 52
#define F_NIT (DDIM / F_ECH)

__global__ __launch_bounds__(F_THREADS)
void fuse_kernel(const float* __restrict__ e2,
                 const float* __restrict__ bg,
                 const float* __restrict__ bb,
                 const float* __restrict__ u,
                 float* __restrict__ out) {
    __shared__ float tS[2][F_ECH][TS_LD];
    __shared__ float e2S[2][F_ECH][128];
    __shared__ float partial[10][128];
    __shared__ float p1dS[64], p1gS[64], uS[64], bgS[64], bbS[64];

    int blk = blockIdx.x;
    int b   = blk >> 7;
    int m   = blk;
    int tid = threadIdx.x;
    int tj  = tid & 15;
    int tk  = tid >> 4;

    const float* trow   = g_t + (size_t)m * TSTRIDE;
    const float* e2b    = e2 + (size_t)b * 128 * DDIM;
    const float* p2drow = g_p2d + (size_t)b * 128 * KDIM;
    const float* p2grow = g_p2g + (size_t)b * 128 * KDIM;

    if (tid < KDIM) {
        p1dS[tid] = g_p1d[m * KDIM + tid];
        p1gS[tid] = g_p1g[m * KDIM + tid];
        uS[tid]   = u[tid];
        bgS[tid]  = bg[tid];
        bbS[tid]  = bb[tid];
    }

    float4 rT0, rT1, rE[4];
    bool t1v = (tid + F_THREADS) < KDIM * (F_ECH / 4);

    auto ldg_chunk = [&](int e0) {
        {
            int idx = tid; int kq = idx / 5, q = idx - kq * 5;
            rT0 = *reinterpret_cast<const float4*>(&trow[kq * DDIM + e0 + 4 * q]);
        }
        if (t1v) {
            int idx = tid + F_THREADS; int kq = idx / 5, q = idx - kq * 5;
            rT1 = *reinterpret_cast<const float4*>(&trow[kq * DDIM + e0 + 4 * q]);
        }
        #pragma unroll
        for (int it = 0; it < 4; it++) {
            int idx = tid + F_THREADS * it; int j = idx / 5, q = idx - j * 5;
            rE[it] = *reinterpret_cast<const float4*>(&e2b[j * DDIM + e0 + 4 * q]);
        }
    };

    auto sts_chunk = [&](int bsel) {
        {
            int idx = tid; int kq = idx / 5, q = idx - kq * 5;
            tS[bsel][4 * q + 0][kq] = rT0.x;
            tS[bsel][4 * q + 1][kq] = rT0.y;
            tS[bsel][4 * q + 2][kq] = rT0.z;
            tS[bsel][4 * q + 3][kq] = rT0.w;
        }
        if (t1v) {
            int idx = tid + F_THREADS; int kq = idx / 5, q = idx - kq * 5;
            tS[bsel][4 * q + 0][kq] = rT1.x;
            tS[bsel][4 * q + 1][kq] = rT1.y;
            tS[bsel][4 * q + 2][kq] = rT1.z;
            tS[bsel][4 * q + 3][kq] = rT1.w;
        }
        #pragma unroll
        for (int it = 0; it < 4; it++) {
            int idx = tid + F_THREADS * it; int j = idx / 5, q = idx - j * 5;
            e2S[bsel][4 * q + 0][j] = rE[it].x;
            e2S[bsel][4 * q + 1][j] = rE[it].y;
            e2S[bsel][4 * q + 2][j] = rE[it].z;
            e2S[bsel][4 * q + 3][j] = rE[it].w;
        }
    };

    float2 acc[5][4];
    #pragma unroll
    for (int kk = 0; kk < 5; kk++)
        #pragma unroll
        for (int jj = 0; jj < 4; jj++) acc[kk][jj] = make_float2(0.f, 0.f);

    ldg_chunk(0);
    sts_chunk(0);
    __syncthreads();

    for (int i = 0; i < F_NIT; i++) {
        if (i + 1 < F_NIT) ldg_chunk((i + 1) * F_ECH);
        int cur = i & 1;
        #pragma unroll 4
        for (int e = 0; e < F_ECH; e++) {
            float a[5];
            #pragma unroll
            for (int kk = 0; kk < 5; kk++) a[kk] = tS[cur][e][tk + 10 * kk];
            #pragma unroll
            for (int jj = 0; jj < 4; jj++) {
                float2 bv = *reinterpret_cast<const float2*>(&e2S[cur][e][2 * (tj + 16 * jj)]);
                #pragma unroll
                for (int kk = 0; kk < 5; kk++)
                    acc[kk][jj] = ffma2(make_float2(a[kk], a[kk]), bv, acc[kk][jj]);
            }
        }
        if (i + 1 < F_NIT) sts_chunk((i + 1) & 1);
        __syncthreads();
    }

    float pj[4][2];
    #pragma unroll
    for (int jj = 0; jj < 4; jj++) { pj[jj][0] = 0.f; pj[jj][1] = 0.f; }

    #pragma unroll
    for (int kk = 0; kk < 5; kk++) {
        int k = tk + 10 * kk;
        float p1d = p1dS[k], p1g = p1gS[k];
        float bgk = bgS[k], uk = uS[k], bk = bbS[k];
        #pragma unroll
        for (int jj = 0; jj < 4; jj++) {
            int j0 = 2 * (tj + 16 * jj);
            #pragma unroll
            for (int l = 0; l < 2; l++) {
                int j = j0 + l;
                float btp = l ? acc[kk][jj].y : acc[kk][jj].x;
                float sd  = p1d + __ldg(&p2drow[j * KDIM + k]);
                float sg  = p1g + __ldg(&p2grow[j * KDIM + k]) + bgk;
                float g   = 1.0f / (1.0f + __expf(-sg));
                float sln = tanhf(sd);
                float mix = fmaf(g, btp - sln, sln) + bk;
                pj[jj][l] = fmaf(uk, mix, pj[jj][l]);
            }
        }
    }

    #pragma unroll
    for (int jj = 0; jj < 4; jj++) {
        int j0 = 2 * (tj + 16 * jj);
        partial[tk][j0]     = pj[jj][0];
        partial[tk][j0 + 1] = pj[jj][1];
    }
    __syncthreads();

    if (tid < 128) {
        float s = 0.f;
        #pragma unroll
        for (int t = 0; t < 10; t++) s += partial[t][tid];
        out[(size_t)blk * 128 + tid] = s;
    }
}

// ---------------------------------------------------------------------------
extern "C" void kernel_launch(void* const* d_in, const int* in_sizes, int n_in,
                              void* d_out, int out_size) {
    const float* e1 = (const float*)d_in[0];
    const float* e2 = (const float*)d_in[1];
    const float* Wb = (const float*)d_in[2];
    const float* Wd = (const float*)d_in[3];
    const float* Wg = (const float*)d_in[4];
    const float* bg = (const float*)d_in[5];
    const float* bb = (const float*)d_in[6];
    const float* u  = (const float*)d_in[7];
    float* out = (float*)d_out;

    constexpr int P_SMEM = (DDIM * KDIM + DDIM * P_RPAD) * sizeof(float);
    cudaFuncSetAttribute(proj_kernel, cudaFuncAttributeMaxDynamicSharedMemorySize, P_SMEM);
    cudaFuncSetAttribute(tmat_mma_kernel, cudaFuncAttributeMaxDynamicSharedMemorySize, MM_SMEM);

    convA_kernel<<<ROWS1, KPAD>>>(e1);
    convB_kernel<<<dim3(10, 10, KDIM), dim3(32, 8)>>>(Wb);
    proj_kernel<<<512, P_THREADS, P_SMEM>>>(e1, e2, Wd, Wg);
    tmat_mma_kernel<<<dim3(ROWS1 / 128, NPAD / 128), MM_THREADS, MM_SMEM>>>();
    fuse_kernel<<<ROWS1, F_THREADS>>>(e2, bg, bb, u, out);
}

// round 7
// speedup vs baseline: 2.0035x; 1.2136x over previous
#include <cuda_runtime.h>
#include <cuda_bf16.h>
#include <math.h>
#include <stdint.h>

#define BDIM 32
#define L1DIM 128
#define L2DIM 128
#define DDIM 300
#define KDIM 50
#define ROWS1 (BDIM * L1DIM)   // 4096
#define ROWS2 (BDIM * L2DIM)   // 4096
#define KPAD 320               // D padded: 5 chunks of 64 bf16
#define NPAD 15104             // 118*128 padded (k,e) rows for Wb'
#define TROW 16000             // t row: 50 k-blocks of 320 (e padded)

// Scratch (__device__ globals; zero-initialized at module load; pad regions
// are never written so they stay zero across graph replays)
__device__ __nv_bfloat16 g_th[(size_t)ROWS1 * TROW];     // 131 MB  t hi
__device__ __nv_bfloat16 g_tl[(size_t)ROWS1 * TROW];     // 131 MB  t lo
__device__ float g_btp[(size_t)BDIM * 6400 * 128];       // 104.9 MB
__device__ float g_p1d[ROWS1 * KDIM];
__device__ float g_p1g[ROWS1 * KDIM];
__device__ float g_p2d[ROWS2 * KDIM];
__device__ float g_p2g[ROWS2 * KDIM];
__device__ __nv_bfloat16 g_e1h[(size_t)ROWS1 * KPAD];
__device__ __nv_bfloat16 g_e1l[(size_t)ROWS1 * KPAD];
__device__ __nv_bfloat16 g_e2h[(size_t)ROWS2 * KPAD];
__device__ __nv_bfloat16 g_e2l[(size_t)ROWS2 * KPAD];
__device__ __nv_bfloat16 g_wbh[(size_t)NPAD * KPAD];     // Wb'[(k,e)][d] hi
__device__ __nv_bfloat16 g_wbl[(size_t)NPAD * KPAD];     // lo

// ---------------------------------------------------------------------------
// helpers (plain sm_80+ PTX)
// ---------------------------------------------------------------------------
__device__ __forceinline__ uint32_t smem_u32(const void* p) {
    uint32_t a;
    asm("{ .reg .u64 t; cvta.to.shared.u64 t, %1; cvt.u32.u64 %0, t; }" : "=r"(a) : "l"(p));
    return a;
}
__device__ __forceinline__ void cpasync16(uint32_t dst, const void* src) {
    asm volatile("cp.async.cg.shared.global [%0], [%1], 16;" :: "r"(dst), "l"(src));
}
__device__ __forceinline__ void ldsm_x4(uint32_t& r0, uint32_t& r1, uint32_t& r2,
                                        uint32_t& r3, uint32_t addr) {
    asm volatile("ldmatrix.sync.aligned.m8n8.x4.shared.b16 {%0,%1,%2,%3}, [%4];"
                 : "=r"(r0), "=r"(r1), "=r"(r2), "=r"(r3) : "r"(addr));
}
__device__ __forceinline__ void mma_bf16(float* c, const uint32_t* a, const uint32_t* b) {
    asm volatile(
        "mma.sync.aligned.m16n8k16.row.col.f32.bf16.bf16.f32 "
        "{%0,%1,%2,%3}, {%4,%5,%6,%7}, {%8,%9}, {%0,%1,%2,%3};"
        : "+f"(c[0]), "+f"(c[1]), "+f"(c[2]), "+f"(c[3])
        : "r"(a[0]), "r"(a[1]), "r"(a[2]), "r"(a[3]), "r"(b[0]), "r"(b[1]));
}
__device__ __forceinline__ float tanh_hw(float x) {
    float y;
    asm("tanh.approx.f32 %0, %1;" : "=f"(y) : "f"(x));
    return y;
}

// ---------------------------------------------------------------------------
// conversion: e1 and e2 fp32 -> bf16 hi/lo (padded to 320 with zeros)
// ---------------------------------------------------------------------------
__global__ void convA_kernel(const float* __restrict__ e1,
                             const float* __restrict__ e2) {
    int m = blockIdx.x;                  // 0..8191
    int d = threadIdx.x;                 // 0..319
    bool s2 = (m >= ROWS1);
    int row = s2 ? m - ROWS1 : m;
    const float* src = s2 ? e2 : e1;
    float v = (d < DDIM) ? src[(size_t)row * DDIM + d] : 0.f;
    __nv_bfloat16 hi = __float2bfloat16(v);
    __nv_bfloat16 lo = __float2bfloat16(v - __bfloat162float(hi));
    if (s2) { g_e2h[(size_t)row * KPAD + d] = hi; g_e2l[(size_t)row * KPAD + d] = lo; }
    else    { g_e1h[(size_t)row * KPAD + d] = hi; g_e1l[(size_t)row * KPAD + d] = lo; }
}

// Wb[k][d][e] -> Wb'[(k*300+e)][d] (transposed per k, padded, split)
__global__ void convB_kernel(const float* __restrict__ Wb) {
    __shared__ float tile[32][33];
    int k  = blockIdx.z;
    int d0 = blockIdx.x * 32;
    int e0 = blockIdx.y * 32;
    int tx = threadIdx.x, ty = threadIdx.y;   // 32 x 8
    #pragma unroll
    for (int q = 0; q < 4; q++) {
        int d = d0 + ty + 8 * q;
        int e = e0 + tx;
        float v = 0.f;
        if (d < DDIM && e < DDIM)
            v = Wb[(size_t)k * DDIM * DDIM + (size_t)d * DDIM + e];
        tile[ty + 8 * q][tx] = v;
    }
    __syncthreads();
    #pragma unroll
    for (int q = 0; q < 4; q++) {
        int e = e0 + ty + 8 * q;
        int d = d0 + tx;
        if (e < DDIM) {
            float v = tile[tx][ty + 8 * q];
            __nv_bfloat16 hi = __float2bfloat16(v);
            __nv_bfloat16 lo = __float2bfloat16(v - __bfloat162float(hi));
            size_t o = (size_t)(k * DDIM + e) * KPAD + d;
            g_wbh[o] = hi;
            g_wbl[o] = lo;
        }
    }
}

// ---------------------------------------------------------------------------
// shared GEMM plumbing: CTA tile 128x128, 8 warps (32x64), KC=64, 3-stage
// ---------------------------------------------------------------------------
#define MM_THREADS 256
#define MM_KC 64
#define MM_ROWB 144                       // 64 bf16 + 8 pad = 144 B row stride
#define ATILE_B (128 * MM_ROWB)           // 18432 B per matrix
#define STAGE_B (4 * ATILE_B)             // Ah, Al, Bh, Bl = 73728
#define MM_SMEM (3 * STAGE_B)             // 221184 B (3 stages)
#define NCHUNK (KPAD / MM_KC)             // 5

// loads one k-chunk (4 tiles: Ah, Al, Bh, Bl) into stage buffer
#define ISSUE_CHUNK(c, aH, aL, bH, bL, astr, bstr)                              \
    do {                                                                        \
        int d0_ = (c) * MM_KC;                                                  \
        uint32_t stage_ = sb + ((c) % 3) * STAGE_B;                             \
        _Pragma("unroll")                                                       \
        for (int it_ = 0; it_ < 16; it_++) {                                    \
            int i_ = tid + MM_THREADS * it_;                                    \
            int mat_ = i_ >> 10;                                                \
            int idx_ = i_ & 1023;                                               \
            int r_ = idx_ >> 3, c4_ = idx_ & 7;                                 \
            const __nv_bfloat16* src_;                                          \
            if (mat_ == 0)      src_ = (aH) + (size_t)r_ * (astr) + d0_ + c4_ * 8; \
            else if (mat_ == 1) src_ = (aL) + (size_t)r_ * (astr) + d0_ + c4_ * 8; \
            else if (mat_ == 2) src_ = (bH) + (size_t)r_ * (bstr) + d0_ + c4_ * 8; \
            else                src_ = (bL) + (size_t)r_ * (bstr) + d0_ + c4_ * 8; \
            cpasync16(stage_ + mat_ * ATILE_B + r_ * MM_ROWB + c4_ * 16, src_); \
        }                                                                       \
        asm volatile("cp.async.commit_group;" ::: "memory");                    \
    } while (0)

#define MAINLOOP_BODY(c)                                                        \
    do {                                                                        \
        uint32_t sA_h = sb + ((c) % 3) * STAGE_B;                               \
        uint32_t sA_l = sA_h + ATILE_B;                                         \
        uint32_t sB_h = sA_h + 2 * ATILE_B;                                     \
        uint32_t sB_l = sA_h + 3 * ATILE_B;                                     \
        _Pragma("unroll")                                                       \
        for (int kk = 0; kk < MM_KC / 16; kk++) {                               \
            uint32_t ah[2][4], al[2][4];                                        \
            _Pragma("unroll")                                                   \
            for (int mt = 0; mt < 2; mt++) {                                    \
                uint32_t aoff = (uint32_t)(wm + mt * 16 + (lane & 15)) * MM_ROWB \
                              + kk * 32 + (lane >> 4) * 16;                     \
                ldsm_x4(ah[mt][0], ah[mt][1], ah[mt][2], ah[mt][3], sA_h + aoff); \
                ldsm_x4(al[mt][0], al[mt][1], al[mt][2], al[mt][3], sA_l + aoff); \
            }                                                                   \
            uint32_t bh[8][2], bl[8][2];                                        \
            _Pragma("unroll")                                                   \
            for (int nq = 0; nq < 4; nq++) {                                    \
                uint32_t brow = (uint32_t)(wn + nq * 16 + (lane & 7) + ((lane >> 4) << 3)); \
                uint32_t boff = brow * MM_ROWB + kk * 32 + ((lane >> 3) & 1) * 16; \
                ldsm_x4(bh[2*nq][0], bh[2*nq][1], bh[2*nq+1][0], bh[2*nq+1][1], sB_h + boff); \
                ldsm_x4(bl[2*nq][0], bl[2*nq][1], bl[2*nq+1][0], bl[2*nq+1][1], sB_l + boff); \
            }                                                                   \
            _Pragma("unroll")                                                   \
            for (int mt = 0; mt < 2; mt++)                                      \
                _Pragma("unroll")                                               \
                for (int nt = 0; nt < 8; nt++) {                                \
                    mma_bf16(acc[mt][nt], ah[mt], bh[nt]);                      \
                    mma_bf16(acc[mt][nt], ah[mt], bl[nt]);                      \
                    mma_bf16(acc[mt][nt], al[mt], bh[nt]);                      \
                }                                                               \
        }                                                                       \
    } while (0)

#define PIPE_WAIT(c)                                                            \
    do {                                                                        \
        if ((c) + 2 < NCHUNK)      asm volatile("cp.async.wait_group 2;" ::: "memory"); \
        else if ((c) + 1 < NCHUNK) asm volatile("cp.async.wait_group 1;" ::: "memory"); \
        else                       asm volatile("cp.async.wait_group 0;" ::: "memory"); \
    } while (0)

// ---------------------------------------------------------------------------
// Stage-1 GEMM:  t[4096 x 15000pad] = e1[4096 x 320] @ Wb'[15104 x 320]^T
// epilogue: split fp32 acc -> bf16 hi/lo into g_th/g_tl (rows padded to 320/k)
// ---------------------------------------------------------------------------
__global__ __launch_bounds__(MM_THREADS, 1)
void tmat_mma_kernel() {
    extern __shared__ char smem[];
    uint32_t sb = smem_u32(smem);
    int tid  = threadIdx.x;
    int lane = tid & 31;
    int w    = tid >> 5;
    int wm   = (w >> 1) * 32;
    int wn   = (w & 1) * 64;
    int m0 = blockIdx.x * 128;
    int n0 = blockIdx.y * 128;

    const __nv_bfloat16* aH = g_e1h + (size_t)m0 * KPAD;
    const __nv_bfloat16* aL = g_e1l + (size_t)m0 * KPAD;
    const __nv_bfloat16* bH = g_wbh + (size_t)n0 * KPAD;
    const __nv_bfloat16* bL = g_wbl + (size_t)n0 * KPAD;

    float acc[2][8][4];
    #pragma unroll
    for (int mt = 0; mt < 2; mt++)
        #pragma unroll
        for (int nt = 0; nt < 8; nt++)
            #pragma unroll
            for (int q = 0; q < 4; q++) acc[mt][nt][q] = 0.f;

    ISSUE_CHUNK(0, aH, aL, bH, bL, KPAD, KPAD);
    ISSUE_CHUNK(1, aH, aL, bH, bL, KPAD, KPAD);

    for (int c = 0; c < NCHUNK; c++) {
        if (c + 2 < NCHUNK) ISSUE_CHUNK(c + 2, aH, aL, bH, bL, KPAD, KPAD);
        PIPE_WAIT(c);
        __syncthreads();
        MAINLOOP_BODY(c);
        __syncthreads();
    }

    // epilogue: fp32 -> bf16 hi/lo, write to g_th/g_tl at m*16000 + k*320 + e
    #pragma unroll
    for (int mt = 0; mt < 2; mt++) {
        int row = m0 + wm + mt * 16 + (lane >> 2);
        #pragma unroll
        for (int nt = 0; nt < 8; nt++) {
            int col = n0 + wn + nt * 8 + 2 * (lane & 3);
            if (col < KDIM * DDIM) {
                int k = col / DDIM;
                int e = col - k * DDIM;
                size_t off = (size_t)row * TROW + k * KPAD + e;
                #pragma unroll
                for (int rr = 0; rr < 2; rr++) {
                    float c0 = acc[mt][nt][2 * rr];
                    float c1 = acc[mt][nt][2 * rr + 1];
                    __nv_bfloat16 h0 = __float2bfloat16(c0);
                    __nv_bfloat16 h1 = __float2bfloat16(c1);
                    __nv_bfloat16 l0 = __float2bfloat16(c0 - __bfloat162float(h0));
                    __nv_bfloat16 l1 = __float2bfloat16(c1 - __bfloat162float(h1));
                    size_t o = off + (size_t)rr * 8 * TROW;
                    *reinterpret_cast<__nv_bfloat162*>(&g_th[o]) = __nv_bfloat162(h0, h1);
                    *reinterpret_cast<__nv_bfloat162*>(&g_tl[o]) = __nv_bfloat162(l0, l1);
                }
            }
        }
    }
}

// ---------------------------------------------------------------------------
// Stage-2 GEMM (per b):  btp[6400 x 128] = T_b[6400 x 320] @ e2_b[128 x 320]^T
// T_b rows r=(i*50+k) are contiguous with stride 320 inside g_th/g_tl.
// ---------------------------------------------------------------------------
__global__ __launch_bounds__(MM_THREADS, 1)
void btp_mma_kernel() {
    extern __shared__ char smem[];
    uint32_t sb = smem_u32(smem);
    int tid  = threadIdx.x;
    int lane = tid & 31;
    int w    = tid >> 5;
    int wm   = (w >> 1) * 32;
    int wn   = (w & 1) * 64;
    int m0 = blockIdx.x * 128;           // row tile in 6400
    int b  = blockIdx.y;

    const __nv_bfloat16* aH = g_th + (size_t)b * 128 * TROW + (size_t)m0 * KPAD;
    const __nv_bfloat16* aL = g_tl + (size_t)b * 128 * TROW + (size_t)m0 * KPAD;
    const __nv_bfloat16* bH = g_e2h + (size_t)b * 128 * KPAD;
    const __nv_bfloat16* bL = g_e2l + (size_t)b * 128 * KPAD;

    float acc[2][8][4];
    #pragma unroll
    for (int mt = 0; mt < 2; mt++)
        #pragma unroll
        for (int nt = 0; nt < 8; nt++)
            #pragma unroll
            for (int q = 0; q < 4; q++) acc[mt][nt][q] = 0.f;

    ISSUE_CHUNK(0, aH, aL, bH, bL, KPAD, KPAD);
    ISSUE_CHUNK(1, aH, aL, bH, bL, KPAD, KPAD);

    for (int c = 0; c < NCHUNK; c++) {
        if (c + 2 < NCHUNK) ISSUE_CHUNK(c + 2, aH, aL, bH, bL, KPAD, KPAD);
        PIPE_WAIT(c);
        __syncthreads();
        MAINLOOP_BODY(c);
        __syncthreads();
    }

    // epilogue: fp32 btp -> g_btp[b][m0+row][col]  (exact tiles, no predicates)
    float* dst = g_btp + (size_t)b * 6400 * 128;
    #pragma unroll
    for (int mt = 0; mt < 2; mt++) {
        int row = m0 + wm + mt * 16 + (lane >> 2);
        float* r0p = dst + (size_t)row * 128;
        float* r1p = r0p + 8 * 128;
        #pragma unroll
        for (int nt = 0; nt < 8; nt++) {
            int col = wn + nt * 8 + 2 * (lane & 3);
            *reinterpret_cast<float2*>(r0p + col) = make_float2(acc[mt][nt][0], acc[mt][nt][1]);
            *reinterpret_cast<float2*>(r1p + col) = make_float2(acc[mt][nt][2], acc[mt][nt][3]);
        }
    }
}

// ---------------------------------------------------------------------------
// gate epilogue: per (b,i) block, 128 threads (j):
//   out[b,i,j] = sum_k u_k * ( g*btp + (1-g)*tanh(sd) + bb_k )
// ---------------------------------------------------------------------------
#define G_P2LD 129
#define G_SMEM ((2 * KDIM * G_P2LD + 5 * 64) * 4)

__global__ __launch_bounds__(128)
void gate_kernel(const float* __restrict__ bg,
                 const float* __restrict__ bb,
                 const float* __restrict__ u,
                 float* __restrict__ out) {
    extern __shared__ float sm[];
    float* p2dS = sm;                     // [50][129]
    float* p2gS = sm + KDIM * G_P2LD;     // [50][129]
    float* p1dS = p2gS + KDIM * G_P2LD;   // [64]
    float* p1gS = p1dS + 64;
    float* uS   = p1gS + 64;
    float* bgS  = uS + 64;
    float* bbS  = bgS + 64;

    int blk = blockIdx.x;                 // b*128 + i
    int b   = blk >> 7;
    int tid = threadIdx.x;                // j

    const float* p2d_b = g_p2d + (size_t)b * 128 * KDIM;
    const float* p2g_b = g_p2g + (size_t)b * 128 * KDIM;
    for (int idx = tid; idx < 128 * KDIM; idx += 128) {
        int j = idx / KDIM, k = idx - j * KDIM;
        p2dS[k * G_P2LD + j] = p2d_b[idx];
        p2gS[k * G_P2LD + j] = p2g_b[idx];
    }
    if (tid < KDIM) {
        p1dS[tid] = g_p1d[(size_t)blk * KDIM + tid];
        p1gS[tid] = g_p1g[(size_t)blk * KDIM + tid];
        uS[tid]   = u[tid];
        bgS[tid]  = bg[tid];
        bbS[tid]  = bb[tid];
    }
    __syncthreads();

    const float* btp_row = g_btp + (size_t)b * 6400 * 128 + (size_t)(blk & 127) * KDIM * 128;

    float acc = 0.f;
    #pragma unroll 5
    for (int k = 0; k < KDIM; k++) {
        float btp = btp_row[k * 128 + tid];
        float sd  = p1dS[k] + p2dS[k * G_P2LD + tid];
        float sg  = p1gS[k] + p2gS[k * G_P2LD + tid] + bgS[k];
        float e   = __expf(-sg);
        float g   = __fdividef(1.f, 1.f + e);
        float sln = tanh_hw(sd);
        float mix = fmaf(g, btp - sln, sln) + bbS[k];
        acc = fmaf(uS[k], mix, acc);
    }
    out[(size_t)blk * 128 + tid] = acc;
}

// ---------------------------------------------------------------------------
// projections (unchanged from round 4)
// ---------------------------------------------------------------------------
#define P_ROWS 32
#define P_THREADS 256
#define P_RPAD 33

__global__ __launch_bounds__(P_THREADS)
void proj_kernel(const float* __restrict__ e1,
                 const float* __restrict__ e2,
                 const float* __restrict__ Wd,
                 const float* __restrict__ Wg) {
    extern __shared__ float sm[];
    float* WS   = sm;
    float* rowS = sm + DDIM * KDIM;

    int blk = blockIdx.x;
    int rt  = blk & 127;
    int mt  = (blk >> 7) & 1;
    int s   = blk >> 8;
    int row0 = rt * P_ROWS;
    int tid = threadIdx.x;

    const float* E = s ? e2 : e1;
    const float* W = (mt ? Wg : Wd) + s * DDIM * KDIM;
    float* out = s ? (mt ? g_p2g : g_p2d) : (mt ? g_p1g : g_p1d);

    const float4* W4 = reinterpret_cast<const float4*>(W);
    float4* WS4 = reinterpret_cast<float4*>(WS);
    for (int i = tid; i < DDIM * KDIM / 4; i += P_THREADS) WS4[i] = W4[i];

    for (int i = tid; i < P_ROWS * (DDIM / 4); i += P_THREADS) {
        int r = i / (DDIM / 4);
        int c4 = i % (DDIM / 4);
        float4 v = *reinterpret_cast<const float4*>(&E[(size_t)(row0 + r) * DDIM + 4 * c4]);
        rowS[(4 * c4 + 0) * P_RPAD + r] = v.x;
        rowS[(4 * c4 + 1) * P_RPAD + r] = v.y;
        rowS[(4 * c4 + 2) * P_RPAD + r] = v.z;
        rowS[(4 * c4 + 3) * P_RPAD + r] = v.w;
    }
    __syncthreads();

    int r  = tid & 31;
    int k0 = tid >> 5;
    float acc[7];
    #pragma unroll
    for (int t = 0; t < 7; t++) acc[t] = 0.f;

    #pragma unroll 4
    for (int d = 0; d < DDIM; d++) {
        float x = rowS[d * P_RPAD + r];
        const float* wrow = &WS[d * KDIM + k0];
        #pragma unroll
        for (int t = 0; t < 7; t++)
            acc[t] = fmaf(x, wrow[8 * t], acc[t]);
    }

    #pragma unroll
    for (int t = 0; t < 7; t++) {
        int k = k0 + 8 * t;
        if (k < KDIM) out[(size_t)(row0 + r) * KDIM + k] = acc[t];
    }
}

// ---------------------------------------------------------------------------
extern "C" void kernel_launch(void* const* d_in, const int* in_sizes, int n_in,
                              void* d_out, int out_size) {
    const float* e1 = (const float*)d_in[0];
    const float* e2 = (const float*)d_in[1];
    const float* Wb = (const float*)d_in[2];
    const float* Wd = (const float*)d_in[3];
    const float* Wg = (const float*)d_in[4];
    const float* bg = (const float*)d_in[5];
    const float* bb = (const float*)d_in[6];
    const float* u  = (const float*)d_in[7];
    float* out = (float*)d_out;

    constexpr int P_SMEM = (DDIM * KDIM + DDIM * P_RPAD) * sizeof(float);
    cudaFuncSetAttribute(proj_kernel, cudaFuncAttributeMaxDynamicSharedMemorySize, P_SMEM);
    cudaFuncSetAttribute(tmat_mma_kernel, cudaFuncAttributeMaxDynamicSharedMemorySize, MM_SMEM);
    cudaFuncSetAttribute(btp_mma_kernel, cudaFuncAttributeMaxDynamicSharedMemorySize, MM_SMEM);
    cudaFuncSetAttribute(gate_kernel, cudaFuncAttributeMaxDynamicSharedMemorySize, G_SMEM);

    convA_kernel<<<2 * ROWS1, KPAD>>>(e1, e2);
    convB_kernel<<<dim3(10, 10, KDIM), dim3(32, 8)>>>(Wb);
    proj_kernel<<<512, P_THREADS, P_SMEM>>>(e1, e2, Wd, Wg);
    tmat_mma_kernel<<<dim3(ROWS1 / 128, NPAD / 128), MM_THREADS, MM_SMEM>>>();
    btp_mma_kernel<<<dim3(6400 / 128, BDIM), MM_THREADS, MM_SMEM>>>();
    gate_kernel<<<ROWS1, 128, G_SMEM>>>(bg, bb, u, out);
}

// round 8
// speedup vs baseline: 2.0252x; 1.0108x over previous
#include <cuda_runtime.h>
#include <cuda_bf16.h>
#include <math.h>
#include <stdint.h>

#define BDIM 32
#define L1DIM 128
#define L2DIM 128
#define DDIM 300
#define KDIM 50
#define ROWS1 (BDIM * L1DIM)   // 4096
#define ROWS2 (BDIM * L2DIM)   // 4096
#define KPAD 320               // D padded: 5 chunks of 64 bf16
#define TROW (KDIM * KPAD)     // 16000: t row AND Wb'' row count (k*320+e)

// Scratch (__device__ globals; zero-initialized at module load; pad regions
// never written so they stay zero across graph replays)
__device__ __nv_bfloat16 g_th[(size_t)ROWS1 * TROW];     // 131 MB
__device__ __nv_bfloat16 g_tl[(size_t)ROWS1 * TROW];     // 131 MB
__device__ float g_btp[(size_t)BDIM * 6400 * 128];       // 104.9 MB
__device__ float g_p1d[ROWS1 * KDIM];
__device__ float g_p1g[ROWS1 * KDIM];
__device__ float g_p2d[ROWS2 * KDIM];
__device__ float g_p2g[ROWS2 * KDIM];
__device__ __nv_bfloat16 g_e1h[(size_t)ROWS1 * KPAD];
__device__ __nv_bfloat16 g_e1l[(size_t)ROWS1 * KPAD];
__device__ __nv_bfloat16 g_e2h[(size_t)ROWS2 * KPAD];
__device__ __nv_bfloat16 g_e2l[(size_t)ROWS2 * KPAD];
__device__ __nv_bfloat16 g_wbh[(size_t)TROW * KPAD];     // Wb''[(k*320+e)][d] hi
__device__ __nv_bfloat16 g_wbl[(size_t)TROW * KPAD];     // lo

// ---------------------------------------------------------------------------
// helpers (plain sm_80+ PTX)
// ---------------------------------------------------------------------------
__device__ __forceinline__ uint32_t smem_u32(const void* p) {
    uint32_t a;
    asm("{ .reg .u64 t; cvta.to.shared.u64 t, %1; cvt.u32.u64 %0, t; }" : "=r"(a) : "l"(p));
    return a;
}
__device__ __forceinline__ void cpasync16(uint32_t dst, const void* src) {
    asm volatile("cp.async.cg.shared.global [%0], [%1], 16;" :: "r"(dst), "l"(src));
}
__device__ __forceinline__ void ldsm_x4(uint32_t& r0, uint32_t& r1, uint32_t& r2,
                                        uint32_t& r3, uint32_t addr) {
    asm volatile("ldmatrix.sync.aligned.m8n8.x4.shared.b16 {%0,%1,%2,%3}, [%4];"
                 : "=r"(r0), "=r"(r1), "=r"(r2), "=r"(r3) : "r"(addr));
}
__device__ __forceinline__ void mma_bf16(float* c, const uint32_t* a, const uint32_t* b) {
    asm volatile(
        "mma.sync.aligned.m16n8k16.row.col.f32.bf16.bf16.f32 "
        "{%0,%1,%2,%3}, {%4,%5,%6,%7}, {%8,%9}, {%0,%1,%2,%3};"
        : "+f"(c[0]), "+f"(c[1]), "+f"(c[2]), "+f"(c[3])
        : "r"(a[0]), "r"(a[1]), "r"(a[2]), "r"(a[3]), "r"(b[0]), "r"(b[1]));
}
__device__ __forceinline__ float tanh_hw(float x) {
    float y;
    asm("tanh.approx.f32 %0, %1;" : "=f"(y) : "f"(x));
    return y;
}

// ---------------------------------------------------------------------------
// conversion: e1/e2 fp32 -> bf16 hi/lo (padded to 320 with zeros)
// ---------------------------------------------------------------------------
__global__ void convA_kernel(const float* __restrict__ e1,
                             const float* __restrict__ e2) {
    int m = blockIdx.x;
    int d = threadIdx.x;                 // 0..319
    bool s2 = (m >= ROWS1);
    int row = s2 ? m - ROWS1 : m;
    const float* src = s2 ? e2 : e1;
    float v = (d < DDIM) ? src[(size_t)row * DDIM + d] : 0.f;
    __nv_bfloat16 hi = __float2bfloat16(v);
    __nv_bfloat16 lo = __float2bfloat16(v - __bfloat162float(hi));
    if (s2) { g_e2h[(size_t)row * KPAD + d] = hi; g_e2l[(size_t)row * KPAD + d] = lo; }
    else    { g_e1h[(size_t)row * KPAD + d] = hi; g_e1l[(size_t)row * KPAD + d] = lo; }
}

// Wb[k][d][e] -> Wb''[(k*320+e)][d]  (transposed per k, e rows padded, split)
__global__ void convB_kernel(const float* __restrict__ Wb) {
    __shared__ float tile[32][33];
    int k  = blockIdx.z;
    int d0 = blockIdx.x * 32;
    int e0 = blockIdx.y * 32;
    int tx = threadIdx.x, ty = threadIdx.y;   // 32 x 8
    #pragma unroll
    for (int q = 0; q < 4; q++) {
        int d = d0 + ty + 8 * q;
        int e = e0 + tx;
        float v = 0.f;
        if (d < DDIM && e < DDIM)
            v = Wb[(size_t)k * DDIM * DDIM + (size_t)d * DDIM + e];
        tile[ty + 8 * q][tx] = v;
    }
    __syncthreads();
    #pragma unroll
    for (int q = 0; q < 4; q++) {
        int e = e0 + ty + 8 * q;
        int d = d0 + tx;
        if (e < DDIM) {
            float v = tile[tx][ty + 8 * q];
            __nv_bfloat16 hi = __float2bfloat16(v);
            __nv_bfloat16 lo = __float2bfloat16(v - __bfloat162float(hi));
            size_t o = ((size_t)k * KPAD + e) * KPAD + d;
            g_wbh[o] = hi;
            g_wbl[o] = lo;
        }
    }
}

// ---------------------------------------------------------------------------
// GEMM plumbing: CTA tile 128x64, 8 warps (warp 32x32), KC=64, 2-stage,
// 110.6 KB smem -> 2 CTAs/SM. A = 128 rows, B = 64 rows, stride KPAD.
// ---------------------------------------------------------------------------
#define MM_THREADS 256
#define MM_KC 64
#define MM_ROWB 144                       // 64 bf16 (128B) + 16B pad
#define A_TILE_B (128 * MM_ROWB)          // 18432
#define B_TILE_B (64 * MM_ROWB)           // 9216
#define STAGE_B (2 * A_TILE_B + 2 * B_TILE_B)   // 55296
#define MM_SMEM (2 * STAGE_B)             // 110592
#define NCHUNK (KPAD / MM_KC)             // 5

struct GemmCore {
    uint32_t sb;
    int tid, lane, wm, wn;
    const __nv_bfloat16 *aH, *aL, *bH, *bL;
    float acc[2][4][4];

    __device__ __forceinline__ void init(uint32_t sb_, int tid_,
                                         const __nv_bfloat16* aH_, const __nv_bfloat16* aL_,
                                         const __nv_bfloat16* bH_, const __nv_bfloat16* bL_) {
        sb = sb_; tid = tid_;
        lane = tid & 31;
        int w = tid >> 5;
        wm = (w >> 1) * 32;
        wn = (w & 1) * 32;
        aH = aH_; aL = aL_; bH = bH_; bL = bL_;
        #pragma unroll
        for (int mt = 0; mt < 2; mt++)
            #pragma unroll
            for (int nt = 0; nt < 4; nt++)
                #pragma unroll
                for (int q = 0; q < 4; q++) acc[mt][nt][q] = 0.f;
    }

    __device__ __forceinline__ void issue(int c) {
        int d0 = c * MM_KC;
        uint32_t stage = sb + (c & 1) * STAGE_B;
        #pragma unroll
        for (int it = 0; it < 12; it++) {
            int i = tid + MM_THREADS * it;
            if (it < 8) {   // A tiles: 2 x 1024 float4
                int mat = i >> 10;
                int idx = i & 1023;
                int r = idx >> 3, c4 = idx & 7;
                const __nv_bfloat16* src = (mat ? aL : aH) + (size_t)r * KPAD + d0 + c4 * 8;
                cpasync16(stage + mat * A_TILE_B + r * MM_ROWB + c4 * 16, src);
            } else {        // B tiles: 2 x 512 float4
                int j = i - 2048;
                int mat = j >> 9;
                int idx = j & 511;
                int r = idx >> 3, c4 = idx & 7;
                const __nv_bfloat16* src = (mat ? bL : bH) + (size_t)r * KPAD + d0 + c4 * 8;
                cpasync16(stage + 2 * A_TILE_B + mat * B_TILE_B + r * MM_ROWB + c4 * 16, src);
            }
        }
        asm volatile("cp.async.commit_group;" ::: "memory");
    }

    __device__ __forceinline__ void compute(int c) {
        uint32_t sA_h = sb + (c & 1) * STAGE_B;
        uint32_t sA_l = sA_h + A_TILE_B;
        uint32_t sB_h = sA_h + 2 * A_TILE_B;
        uint32_t sB_l = sB_h + B_TILE_B;
        #pragma unroll
        for (int kk = 0; kk < MM_KC / 16; kk++) {
            uint32_t ah[2][4], al[2][4];
            #pragma unroll
            for (int mt = 0; mt < 2; mt++) {
                uint32_t aoff = (uint32_t)(wm + mt * 16 + (lane & 15)) * MM_ROWB
                              + kk * 32 + (lane >> 4) * 16;
                ldsm_x4(ah[mt][0], ah[mt][1], ah[mt][2], ah[mt][3], sA_h + aoff);
                ldsm_x4(al[mt][0], al[mt][1], al[mt][2], al[mt][3], sA_l + aoff);
            }
            uint32_t bh[4][2], bl[4][2];
            #pragma unroll
            for (int nq = 0; nq < 2; nq++) {
                uint32_t brow = (uint32_t)(wn + nq * 16 + (lane & 7) + ((lane >> 4) << 3));
                uint32_t boff = brow * MM_ROWB + kk * 32 + ((lane >> 3) & 1) * 16;
                ldsm_x4(bh[2*nq][0], bh[2*nq][1], bh[2*nq+1][0], bh[2*nq+1][1], sB_h + boff);
                ldsm_x4(bl[2*nq][0], bl[2*nq][1], bl[2*nq+1][0], bl[2*nq+1][1], sB_l + boff);
            }
            #pragma unroll
            for (int mt = 0; mt < 2; mt++)
                #pragma unroll
                for (int nt = 0; nt < 4; nt++) {
                    mma_bf16(acc[mt][nt], ah[mt], bh[nt]);
                    mma_bf16(acc[mt][nt], ah[mt], bl[nt]);
                    mma_bf16(acc[mt][nt], al[mt], bh[nt]);
                }
        }
    }

    __device__ __forceinline__ void run() {
        issue(0);
        issue(1);
        for (int c = 0; c < NCHUNK; c++) {
            if (c + 1 < NCHUNK) {
                asm volatile("cp.async.wait_group 1;" ::: "memory");
            } else {
                asm volatile("cp.async.wait_group 0;" ::: "memory");
            }
            __syncthreads();
            compute(c);
            __syncthreads();
            if (c + 2 < NCHUNK) issue(c + 2);
        }
    }
};

// ---------------------------------------------------------------------------
// Stage-1: t[4096 x 16000] = e1[4096 x 320] @ Wb''[16000 x 320]^T
// column index == storage offset (k*320+e); epilogue splits to bf16 hi/lo.
// ---------------------------------------------------------------------------
__global__ __launch_bounds__(MM_THREADS, 2)
void tmat_mma_kernel() {
    extern __shared__ char smem[];
    GemmCore g;
    int m0 = blockIdx.x * 128;
    int n0 = blockIdx.y * 64;
    g.init(smem_u32(smem), threadIdx.x,
           g_e1h + (size_t)m0 * KPAD, g_e1l + (size_t)m0 * KPAD,
           g_wbh + (size_t)n0 * KPAD, g_wbl + (size_t)n0 * KPAD);
    g.run();

    #pragma unroll
    for (int mt = 0; mt < 2; mt++) {
        int row = m0 + g.wm + mt * 16 + (g.lane >> 2);
        size_t base = (size_t)row * TROW + n0 + g.wn;
        #pragma unroll
        for (int nt = 0; nt < 4; nt++) {
            int coff = nt * 8 + 2 * (g.lane & 3);
            #pragma unroll
            for (int rr = 0; rr < 2; rr++) {
                float c0 = g.acc[mt][nt][2 * rr];
                float c1 = g.acc[mt][nt][2 * rr + 1];
                __nv_bfloat16 h0 = __float2bfloat16(c0);
                __nv_bfloat16 h1 = __float2bfloat16(c1);
                __nv_bfloat16 l0 = __float2bfloat16(c0 - __bfloat162float(h0));
                __nv_bfloat16 l1 = __float2bfloat16(c1 - __bfloat162float(h1));
                size_t o = base + coff + (size_t)rr * 8 * TROW;
                *reinterpret_cast<__nv_bfloat162*>(&g_th[o]) = __nv_bfloat162(h0, h1);
                *reinterpret_cast<__nv_bfloat162*>(&g_tl[o]) = __nv_bfloat162(l0, l1);
            }
        }
    }
}

// ---------------------------------------------------------------------------
// Stage-2 (per b): btp[6400 x 128] = T_b[6400 x 320] @ e2_b[128 x 320]^T
// ---------------------------------------------------------------------------
__global__ __launch_bounds__(MM_THREADS, 2)
void btp_mma_kernel() {
    extern __shared__ char smem[];
    GemmCore g;
    int m0 = blockIdx.x * 128;           // in 6400
    int n0 = blockIdx.y * 64;            // in 128
    int b  = blockIdx.z;
    size_t abase = (size_t)b * 128 * TROW + (size_t)m0 * KPAD;
    g.init(smem_u32(smem), threadIdx.x,
           g_th + abase, g_tl + abase,
           g_e2h + (size_t)(b * 128 + n0) * KPAD,
           g_e2l + (size_t)(b * 128 + n0) * KPAD);
    g.run();

    float* dst = g_btp + (size_t)b * 6400 * 128;
    #pragma unroll
    for (int mt = 0; mt < 2; mt++) {
        int row = m0 + g.wm + mt * 16 + (g.lane >> 2);
        float* r0p = dst + (size_t)row * 128 + n0 + g.wn;
        float* r1p = r0p + 8 * 128;
        #pragma unroll
        for (int nt = 0; nt < 4; nt++) {
            int coff = nt * 8 + 2 * (g.lane & 3);
            *reinterpret_cast<float2*>(r0p + coff) = make_float2(g.acc[mt][nt][0], g.acc[mt][nt][1]);
            *reinterpret_cast<float2*>(r1p + coff) = make_float2(g.acc[mt][nt][2], g.acc[mt][nt][3]);
        }
    }
}

// ---------------------------------------------------------------------------
// gate epilogue: out[b,i,j] = sum_k u_k*( g*btp + (1-g)*tanh(sd) + bb_k )
// ---------------------------------------------------------------------------
#define G_P2LD 129
#define G_SMEM ((2 * KDIM * G_P2LD + 5 * 64) * 4)

__global__ __launch_bounds__(128)
void gate_kernel(const float* __restrict__ bg,
                 const float* __restrict__ bb,
                 const float* __restrict__ u,
                 float* __restrict__ out) {
    extern __shared__ float sm[];
    float* p2dS = sm;
    float* p2gS = sm + KDIM * G_P2LD;
    float* p1dS = p2gS + KDIM * G_P2LD;
    float* p1gS = p1dS + 64;
    float* uS   = p1gS + 64;
    float* bgS  = uS + 64;
    float* bbS  = bgS + 64;

    int blk = blockIdx.x;                 // b*128 + i
    int b   = blk >> 7;
    int tid = threadIdx.x;                // j

    const float* p2d_b = g_p2d + (size_t)b * 128 * KDIM;
    const float* p2g_b = g_p2g + (size_t)b * 128 * KDIM;
    for (int idx = tid; idx < 128 * KDIM; idx += 128) {
        int j = idx / KDIM, k = idx - j * KDIM;
        p2dS[k * G_P2LD + j] = p2d_b[idx];
        p2gS[k * G_P2LD + j] = p2g_b[idx];
    }
    if (tid < KDIM) {
        p1dS[tid] = g_p1d[(size_t)blk * KDIM + tid];
        p1gS[tid] = g_p1g[(size_t)blk * KDIM + tid];
        uS[tid]   = u[tid];
        bgS[tid]  = bg[tid];
        bbS[tid]  = bb[tid];
    }
    __syncthreads();

    const float* btp_row = g_btp + (size_t)b * 6400 * 128 + (size_t)(blk & 127) * KDIM * 128;

    float acc = 0.f;
    #pragma unroll 5
    for (int k = 0; k < KDIM; k++) {
        float btp = btp_row[k * 128 + tid];
        float sd  = p1dS[k] + p2dS[k * G_P2LD + tid];
        float sg  = p1gS[k] + p2gS[k * G_P2LD + tid] + bgS[k];
        float e   = __expf(-sg);
        float g   = __fdividef(1.f, 1.f + e);
        float sln = tanh_hw(sd);
        float mix = fmaf(g, btp - sln, sln) + bbS[k];
        acc = fmaf(uS[k], mix, acc);
    }
    out[(size_t)blk * 128 + tid] = acc;
}

// ---------------------------------------------------------------------------
// projections (unchanged)
// ---------------------------------------------------------------------------
#define P_ROWS 32
#define P_THREADS 256
#define P_RPAD 33

__global__ __launch_bounds__(P_THREADS)
void proj_kernel(const float* __restrict__ e1,
                 const float* __restrict__ e2,
                 const float* __restrict__ Wd,
                 const float* __restrict__ Wg) {
    extern __shared__ float sm[];
    float* WS   = sm;
    float* rowS = sm + DDIM * KDIM;

    int blk = blockIdx.x;
    int rt  = blk & 127;
    int mt  = (blk >> 7) & 1;
    int s   = blk >> 8;
    int row0 = rt * P_ROWS;
    int tid = threadIdx.x;

    const float* E = s ? e2 : e1;
    const float* W = (mt ? Wg : Wd) + s * DDIM * KDIM;
    float* out = s ? (mt ? g_p2g : g_p2d) : (mt ? g_p1g : g_p1d);

    const float4* W4 = reinterpret_cast<const float4*>(W);
    float4* WS4 = reinterpret_cast<float4*>(WS);
    for (int i = tid; i < DDIM * KDIM / 4; i += P_THREADS) WS4[i] = W4[i];

    for (int i = tid; i < P_ROWS * (DDIM / 4); i += P_THREADS) {
        int r = i / (DDIM / 4);
        int c4 = i % (DDIM / 4);
        float4 v = *reinterpret_cast<const float4*>(&E[(size_t)(row0 + r) * DDIM + 4 * c4]);
        rowS[(4 * c4 + 0) * P_RPAD + r] = v.x;
        rowS[(4 * c4 + 1) * P_RPAD + r] = v.y;
        rowS[(4 * c4 + 2) * P_RPAD + r] = v.z;
        rowS[(4 * c4 + 3) * P_RPAD + r] = v.w;
    }
    __syncthreads();

    int r  = tid & 31;
    int k0 = tid >> 5;
    float acc[7];
    #pragma unroll
    for (int t = 0; t < 7; t++) acc[t] = 0.f;

    #pragma unroll 4
    for (int d = 0; d < DDIM; d++) {
        float x = rowS[d * P_RPAD + r];
        const float* wrow = &WS[d * KDIM + k0];
        #pragma unroll
        for (int t = 0; t < 7; t++)
            acc[t] = fmaf(x, wrow[8 * t], acc[t]);
    }

    #pragma unroll
    for (int t = 0; t < 7; t++) {
        int k = k0 + 8 * t;
        if (k < KDIM) out[(size_t)(row0 + r) * KDIM + k] = acc[t];
    }
}

// ---------------------------------------------------------------------------
extern "C" void kernel_launch(void* const* d_in, const int* in_sizes, int n_in,
                              void* d_out, int out_size) {
    const float* e1 = (const float*)d_in[0];
    const float* e2 = (const float*)d_in[1];
    const float* Wb = (const float*)d_in[2];
    const float* Wd = (const float*)d_in[3];
    const float* Wg = (const float*)d_in[4];
    const float* bg = (const float*)d_in[5];
    const float* bb = (const float*)d_in[6];
    const float* u  = (const float*)d_in[7];
    float* out = (float*)d_out;

    constexpr int P_SMEM = (DDIM * KDIM + DDIM * P_RPAD) * sizeof(float);
    cudaFuncSetAttribute(proj_kernel, cudaFuncAttributeMaxDynamicSharedMemorySize, P_SMEM);
    cudaFuncSetAttribute(tmat_mma_kernel, cudaFuncAttributeMaxDynamicSharedMemorySize, MM_SMEM);
    cudaFuncSetAttribute(btp_mma_kernel, cudaFuncAttributeMaxDynamicSharedMemorySize, MM_SMEM);
    cudaFuncSetAttribute(gate_kernel, cudaFuncAttributeMaxDynamicSharedMemorySize, G_SMEM);

    convA_kernel<<<2 * ROWS1, KPAD>>>(e1, e2);
    convB_kernel<<<dim3(10, 10, KDIM), dim3(32, 8)>>>(Wb);
    proj_kernel<<<512, P_THREADS, P_SMEM>>>(e1, e2, Wd, Wg);
    tmat_mma_kernel<<<dim3(ROWS1 / 128, TROW / 64), MM_THREADS, MM_SMEM>>>();
    btp_mma_kernel<<<dim3(6400 / 128, 2, BDIM), MM_THREADS, MM_SMEM>>>();
    gate_kernel<<<ROWS1, 128, G_SMEM>>>(bg, bb, u, out);
}

// round 9
// speedup vs baseline: 2.0835x; 1.0288x over previous
#include <cuda_runtime.h>
#include <cuda_bf16.h>
#include <math.h>
#include <stdint.h>

#define BDIM 32
#define L1DIM 128
#define L2DIM 128
#define DDIM 300
#define KDIM 50
#define ROWS1 (BDIM * L1DIM)   // 4096
#define ROWS2 (BDIM * L2DIM)   // 4096
#define KPAD 320               // D padded: 10 chunks of 32 bf16
#define TROW (KDIM * KPAD)     // 16000: t row AND Wb'' row count (k*320+e)

// Scratch (__device__ globals; zero-initialized at module load; pad regions
// never written so they stay zero across graph replays)
__device__ __nv_bfloat16 g_th[(size_t)ROWS1 * TROW];     // 131 MB
__device__ __nv_bfloat16 g_tl[(size_t)ROWS1 * TROW];     // 131 MB
__device__ float g_btp[(size_t)BDIM * 6400 * 128];       // 104.9 MB
__device__ float g_p1d[ROWS1 * KDIM];
__device__ float g_p1g[ROWS1 * KDIM];
__device__ float g_p2d[ROWS2 * KDIM];
__device__ float g_p2g[ROWS2 * KDIM];
__device__ __nv_bfloat16 g_e1h[(size_t)ROWS1 * KPAD];
__device__ __nv_bfloat16 g_e1l[(size_t)ROWS1 * KPAD];
__device__ __nv_bfloat16 g_e2h[(size_t)ROWS2 * KPAD];
__device__ __nv_bfloat16 g_e2l[(size_t)ROWS2 * KPAD];
__device__ __nv_bfloat16 g_wbh[(size_t)TROW * KPAD];     // Wb''[(k*320+e)][d] hi
__device__ __nv_bfloat16 g_wbl[(size_t)TROW * KPAD];     // lo

// ---------------------------------------------------------------------------
// helpers (plain sm_80+ PTX)
// ---------------------------------------------------------------------------
__device__ __forceinline__ uint32_t smem_u32(const void* p) {
    uint32_t a;
    asm("{ .reg .u64 t; cvta.to.shared.u64 t, %1; cvt.u32.u64 %0, t; }" : "=r"(a) : "l"(p));
    return a;
}
__device__ __forceinline__ void cpasync16(uint32_t dst, const void* src) {
    asm volatile("cp.async.cg.shared.global [%0], [%1], 16;" :: "r"(dst), "l"(src));
}
__device__ __forceinline__ void ldsm_x4(uint32_t& r0, uint32_t& r1, uint32_t& r2,
                                        uint32_t& r3, uint32_t addr) {
    asm volatile("ldmatrix.sync.aligned.m8n8.x4.shared.b16 {%0,%1,%2,%3}, [%4];"
                 : "=r"(r0), "=r"(r1), "=r"(r2), "=r"(r3) : "r"(addr));
}
__device__ __forceinline__ void mma_bf16(float* c, const uint32_t* a, const uint32_t* b) {
    asm volatile(
        "mma.sync.aligned.m16n8k16.row.col.f32.bf16.bf16.f32 "
        "{%0,%1,%2,%3}, {%4,%5,%6,%7}, {%8,%9}, {%0,%1,%2,%3};"
        : "+f"(c[0]), "+f"(c[1]), "+f"(c[2]), "+f"(c[3])
        : "r"(a[0]), "r"(a[1]), "r"(a[2]), "r"(a[3]), "r"(b[0]), "r"(b[1]));
}
__device__ __forceinline__ float tanh_hw(float x) {
    float y;
    asm("tanh.approx.f32 %0, %1;" : "=f"(y) : "f"(x));
    return y;
}

// ---------------------------------------------------------------------------
// conversion: e1/e2 fp32 -> bf16 hi/lo (padded to 320 with zeros)
// ---------------------------------------------------------------------------
__global__ void convA_kernel(const float* __restrict__ e1,
                             const float* __restrict__ e2) {
    int m = blockIdx.x;
    int d = threadIdx.x;                 // 0..319
    bool s2 = (m >= ROWS1);
    int row = s2 ? m - ROWS1 : m;
    const float* src = s2 ? e2 : e1;
    float v = (d < DDIM) ? src[(size_t)row * DDIM + d] : 0.f;
    __nv_bfloat16 hi = __float2bfloat16(v);
    __nv_bfloat16 lo = __float2bfloat16(v - __bfloat162float(hi));
    if (s2) { g_e2h[(size_t)row * KPAD + d] = hi; g_e2l[(size_t)row * KPAD + d] = lo; }
    else    { g_e1h[(size_t)row * KPAD + d] = hi; g_e1l[(size_t)row * KPAD + d] = lo; }
}

// Wb[k][d][e] -> Wb''[(k*320+e)][d]  (transposed per k, e rows padded, split)
__global__ void convB_kernel(const float* __restrict__ Wb) {
    __shared__ float tile[32][33];
    int k  = blockIdx.z;
    int d0 = blockIdx.x * 32;
    int e0 = blockIdx.y * 32;
    int tx = threadIdx.x, ty = threadIdx.y;   // 32 x 8
    #pragma unroll
    for (int q = 0; q < 4; q++) {
        int d = d0 + ty + 8 * q;
        int e = e0 + tx;
        float v = 0.f;
        if (d < DDIM && e < DDIM)
            v = Wb[(size_t)k * DDIM * DDIM + (size_t)d * DDIM + e];
        tile[ty + 8 * q][tx] = v;
    }
    __syncthreads();
    #pragma unroll
    for (int q = 0; q < 4; q++) {
        int e = e0 + ty + 8 * q;
        int d = d0 + tx;
        if (e < DDIM) {
            float v = tile[tx][ty + 8 * q];
            __nv_bfloat16 hi = __float2bfloat16(v);
            __nv_bfloat16 lo = __float2bfloat16(v - __bfloat162float(hi));
            size_t o = ((size_t)k * KPAD + e) * KPAD + d;
            g_wbh[o] = hi;
            g_wbl[o] = lo;
        }
    }
}

// ---------------------------------------------------------------------------
// GEMM: CTA tile 128x128, 8 warps as 2(m) x 4(n) -> warp tile 64x32,
// KC=32, 2-stage cp.async, 80 KB smem -> 2 CTAs/SM.
// ---------------------------------------------------------------------------
#define MM_THREADS 256
#define MM_KC 32
#define MM_ROWB 80                        // 32 bf16 (64B) + 16B pad
#define A_TILE_B (128 * MM_ROWB)          // 10240
#define B_TILE_B (128 * MM_ROWB)          // 10240
#define STAGE_B (2 * A_TILE_B + 2 * B_TILE_B)   // 40960
#define MM_SMEM (2 * STAGE_B)             // 81920
#define NCHUNK (KPAD / MM_KC)             // 10

struct GemmCore {
    uint32_t sb;
    int tid, lane, wm, wn;
    const __nv_bfloat16 *aH, *aL, *bH, *bL;
    float acc[4][4][4];

    __device__ __forceinline__ void init(uint32_t sb_, int tid_,
                                         const __nv_bfloat16* aH_, const __nv_bfloat16* aL_,
                                         const __nv_bfloat16* bH_, const __nv_bfloat16* bL_) {
        sb = sb_; tid = tid_;
        lane = tid & 31;
        int w = tid >> 5;
        wm = (w >> 2) * 64;               // 0 or 64
        wn = (w & 3) * 32;                // 0,32,64,96
        aH = aH_; aL = aL_; bH = bH_; bL = bL_;
        #pragma unroll
        for (int mt = 0; mt < 4; mt++)
            #pragma unroll
            for (int nt = 0; nt < 4; nt++)
                #pragma unroll
                for (int q = 0; q < 4; q++) acc[mt][nt][q] = 0.f;
    }

    __device__ __forceinline__ void issue(int c) {
        int d0 = c * MM_KC;
        uint32_t stage = sb + (c & 1) * STAGE_B;
        #pragma unroll
        for (int it = 0; it < 8; it++) {
            int i = tid + MM_THREADS * it;        // 0..2047
            bool isA = (i < 1024);
            int j   = i & 1023;
            int mat = j >> 9;                      // hi/lo
            int idx = j & 511;
            int r = idx >> 2, c4 = idx & 3;        // 128 rows x 4 float4
            const __nv_bfloat16* src =
                (isA ? (mat ? aL : aH) : (mat ? bL : bH)) + (size_t)r * KPAD + d0 + c4 * 8;
            uint32_t dst = stage + (isA ? mat * A_TILE_B
                                        : 2 * A_TILE_B + mat * B_TILE_B)
                         + r * MM_ROWB + c4 * 16;
            cpasync16(dst, src);
        }
        asm volatile("cp.async.commit_group;" ::: "memory");
    }

    __device__ __forceinline__ void compute(int c) {
        uint32_t sA_h = sb + (c & 1) * STAGE_B;
        uint32_t sA_l = sA_h + A_TILE_B;
        uint32_t sB_h = sA_h + 2 * A_TILE_B;
        uint32_t sB_l = sB_h + B_TILE_B;
        #pragma unroll
        for (int kk = 0; kk < MM_KC / 16; kk++) {
            uint32_t koff = kk * 32 + (lane >> 4) * 16;
            uint32_t ah[4][4];
            #pragma unroll
            for (int mt = 0; mt < 4; mt++) {
                uint32_t aoff = (uint32_t)(wm + mt * 16 + (lane & 15)) * MM_ROWB + koff;
                ldsm_x4(ah[mt][0], ah[mt][1], ah[mt][2], ah[mt][3], sA_h + aoff);
            }
            uint32_t bh[4][2], bl[4][2];
            #pragma unroll
            for (int nq = 0; nq < 2; nq++) {
                uint32_t brow = (uint32_t)(wn + nq * 16 + (lane & 7) + ((lane >> 4) << 3));
                uint32_t boff = brow * MM_ROWB + kk * 32 + ((lane >> 3) & 1) * 16;
                ldsm_x4(bh[2*nq][0], bh[2*nq][1], bh[2*nq+1][0], bh[2*nq+1][1], sB_h + boff);
                ldsm_x4(bl[2*nq][0], bl[2*nq][1], bl[2*nq+1][0], bl[2*nq+1][1], sB_l + boff);
            }
            // passes hh + hl (A-hi live)
            #pragma unroll
            for (int mt = 0; mt < 4; mt++)
                #pragma unroll
                for (int nt = 0; nt < 4; nt++) {
                    mma_bf16(acc[mt][nt], ah[mt], bh[nt]);
                    mma_bf16(acc[mt][nt], ah[mt], bl[nt]);
                }
            // pass lh (A-lo replaces A-hi register footprint)
            uint32_t al[4][4];
            #pragma unroll
            for (int mt = 0; mt < 4; mt++) {
                uint32_t aoff = (uint32_t)(wm + mt * 16 + (lane & 15)) * MM_ROWB + koff;
                ldsm_x4(al[mt][0], al[mt][1], al[mt][2], al[mt][3], sA_l + aoff);
            }
            #pragma unroll
            for (int mt = 0; mt < 4; mt++)
                #pragma unroll
                for (int nt = 0; nt < 4; nt++)
                    mma_bf16(acc[mt][nt], al[mt], bh[nt]);
        }
    }

    __device__ __forceinline__ void run() {
        issue(0);
        issue(1);
        for (int c = 0; c < NCHUNK; c++) {
            if (c + 1 < NCHUNK) {
                asm volatile("cp.async.wait_group 1;" ::: "memory");
            } else {
                asm volatile("cp.async.wait_group 0;" ::: "memory");
            }
            __syncthreads();
            compute(c);
            __syncthreads();
            if (c + 2 < NCHUNK) issue(c + 2);
        }
    }
};

// ---------------------------------------------------------------------------
// Stage-1: t[4096 x 16000] = e1[4096 x 320] @ Wb''[16000 x 320]^T
// ---------------------------------------------------------------------------
__global__ __launch_bounds__(MM_THREADS, 2)
void tmat_mma_kernel() {
    extern __shared__ char smem[];
    GemmCore g;
    int m0 = blockIdx.x * 128;
    int n0 = blockIdx.y * 128;
    g.init(smem_u32(smem), threadIdx.x,
           g_e1h + (size_t)m0 * KPAD, g_e1l + (size_t)m0 * KPAD,
           g_wbh + (size_t)n0 * KPAD, g_wbl + (size_t)n0 * KPAD);
    g.run();

    #pragma unroll
    for (int mt = 0; mt < 4; mt++) {
        int row = m0 + g.wm + mt * 16 + (g.lane >> 2);
        size_t base = (size_t)row * TROW + n0 + g.wn;
        #pragma unroll
        for (int nt = 0; nt < 4; nt++) {
            int coff = nt * 8 + 2 * (g.lane & 3);
            #pragma unroll
            for (int rr = 0; rr < 2; rr++) {
                float c0 = g.acc[mt][nt][2 * rr];
                float c1 = g.acc[mt][nt][2 * rr + 1];
                __nv_bfloat16 h0 = __float2bfloat16(c0);
                __nv_bfloat16 h1 = __float2bfloat16(c1);
                __nv_bfloat16 l0 = __float2bfloat16(c0 - __bfloat162float(h0));
                __nv_bfloat16 l1 = __float2bfloat16(c1 - __bfloat162float(h1));
                size_t o = base + coff + (size_t)rr * 8 * TROW;
                *reinterpret_cast<__nv_bfloat162*>(&g_th[o]) = __nv_bfloat162(h0, h1);
                *reinterpret_cast<__nv_bfloat162*>(&g_tl[o]) = __nv_bfloat162(l0, l1);
            }
        }
    }
}

// ---------------------------------------------------------------------------
// Stage-2 (per b): btp[6400 x 128] = T_b[6400 x 320] @ e2_b[128 x 320]^T
// ---------------------------------------------------------------------------
__global__ __launch_bounds__(MM_THREADS, 2)
void btp_mma_kernel() {
    extern __shared__ char smem[];
    GemmCore g;
    int m0 = blockIdx.x * 128;           // in 6400
    int b  = blockIdx.z;
    size_t abase = (size_t)b * 128 * TROW + (size_t)m0 * KPAD;
    g.init(smem_u32(smem), threadIdx.x,
           g_th + abase, g_tl + abase,
           g_e2h + (size_t)b * 128 * KPAD,
           g_e2l + (size_t)b * 128 * KPAD);
    g.run();

    float* dst = g_btp + (size_t)b * 6400 * 128;
    #pragma unroll
    for (int mt = 0; mt < 4; mt++) {
        int row = m0 + g.wm + mt * 16 + (g.lane >> 2);
        float* r0p = dst + (size_t)row * 128 + g.wn;
        float* r1p = r0p + 8 * 128;
        #pragma unroll
        for (int nt = 0; nt < 4; nt++) {
            int coff = nt * 8 + 2 * (g.lane & 3);
            *reinterpret_cast<float2*>(r0p + coff) = make_float2(g.acc[mt][nt][0], g.acc[mt][nt][1]);
            *reinterpret_cast<float2*>(r1p + coff) = make_float2(g.acc[mt][nt][2], g.acc[mt][nt][3]);
        }
    }
}

// ---------------------------------------------------------------------------
// gate epilogue: out[b,i,j] = sum_k u_k*( g*btp + (1-g)*tanh(sd) + bb_k )
// ---------------------------------------------------------------------------
#define G_P2LD 129
#define G_SMEM ((2 * KDIM * G_P2LD + 5 * 64) * 4)

__global__ __launch_bounds__(128)
void gate_kernel(const float* __restrict__ bg,
                 const float* __restrict__ bb,
                 const float* __restrict__ u,
                 float* __restrict__ out) {
    extern __shared__ float sm[];
    float* p2dS = sm;
    float* p2gS = sm + KDIM * G_P2LD;
    float* p1dS = p2gS + KDIM * G_P2LD;
    float* p1gS = p1dS + 64;
    float* uS   = p1gS + 64;
    float* bgS  = uS + 64;
    float* bbS  = bgS + 64;

    int blk = blockIdx.x;                 // b*128 + i
    int b   = blk >> 7;
    int tid = threadIdx.x;                // j

    const float* p2d_b = g_p2d + (size_t)b * 128 * KDIM;
    const float* p2g_b = g_p2g + (size_t)b * 128 * KDIM;
    for (int idx = tid; idx < 128 * KDIM; idx += 128) {
        int j = idx / KDIM, k = idx - j * KDIM;
        p2dS[k * G_P2LD + j] = p2d_b[idx];
        p2gS[k * G_P2LD + j] = p2g_b[idx];
    }
    if (tid < KDIM) {
        p1dS[tid] = g_p1d[(size_t)blk * KDIM + tid];
        p1gS[tid] = g_p1g[(size_t)blk * KDIM + tid];
        uS[tid]   = u[tid];
        bgS[tid]  = bg[tid];
        bbS[tid]  = bb[tid];
    }
    __syncthreads();

    const float* btp_row = g_btp + (size_t)b * 6400 * 128 + (size_t)(blk & 127) * KDIM * 128;

    float acc = 0.f;
    #pragma unroll 5
    for (int k = 0; k < KDIM; k++) {
        float btp = btp_row[k * 128 + tid];
        float sd  = p1dS[k] + p2dS[k * G_P2LD + tid];
        float sg  = p1gS[k] + p2gS[k * G_P2LD + tid] + bgS[k];
        float e   = __expf(-sg);
        float g   = __fdividef(1.f, 1.f + e);
        float sln = tanh_hw(sd);
        float mix = fmaf(g, btp - sln, sln) + bbS[k];
        acc = fmaf(uS[k], mix, acc);
    }
    out[(size_t)blk * 128 + tid] = acc;
}

// ---------------------------------------------------------------------------
// projections v2: warp = one 4-row group, lanes = consecutive k.
// Per d: one broadcast float4 (rows) + one coalesced W row -> 4 FMA.
// ---------------------------------------------------------------------------
#define P_ROWS 32
#define P_THREADS 512
#define P_SMEM ((DDIM * KDIM + DDIM * P_ROWS) * 4)   // 60000 + 38400 B

__global__ __launch_bounds__(P_THREADS)
void proj_kernel(const float* __restrict__ e1,
                 const float* __restrict__ e2,
                 const float* __restrict__ Wd,
                 const float* __restrict__ Wg) {
    extern __shared__ float sm[];
    float* WS   = sm;                    // [300][50]
    float* rowS = sm + DDIM * KDIM;      // [300][32] transposed, no pad

    int blk = blockIdx.x;
    int rt  = blk & 127;
    int mt  = (blk >> 7) & 1;
    int s   = blk >> 8;
    int row0 = rt * P_ROWS;
    int tid = threadIdx.x;

    const float* E = s ? e2 : e1;
    const float* W = (mt ? Wg : Wd) + s * DDIM * KDIM;
    float* out = s ? (mt ? g_p2g : g_p2d) : (mt ? g_p1g : g_p1d);

    const float4* W4 = reinterpret_cast<const float4*>(W);
    float4* WS4 = reinterpret_cast<float4*>(WS);
    for (int i = tid; i < DDIM * KDIM / 4; i += P_THREADS) WS4[i] = W4[i];

    for (int i = tid; i < P_ROWS * (DDIM / 4); i += P_THREADS) {
        int r = i / (DDIM / 4);
        int c4 = i % (DDIM / 4);
        float4 v = *reinterpret_cast<const float4*>(&E[(size_t)(row0 + r) * DDIM + 4 * c4]);
        rowS[(4 * c4 + 0) * P_ROWS + r] = v.x;
        rowS[(4 * c4 + 1) * P_ROWS + r] = v.y;
        rowS[(4 * c4 + 2) * P_ROWS + r] = v.z;
        rowS[(4 * c4 + 3) * P_ROWS + r] = v.w;
    }
    __syncthreads();

    int k  = tid & 63;                   // lane-consecutive k
    int r4 = tid >> 6;                   // 0..7 -> rows r4*4..r4*4+3
    if (k < KDIM) {
        float4 acc = make_float4(0.f, 0.f, 0.f, 0.f);
        #pragma unroll 4
        for (int d = 0; d < DDIM; d++) {
            float4 x = *reinterpret_cast<const float4*>(&rowS[d * P_ROWS + r4 * 4]);
            float w = WS[d * KDIM + k];
            acc.x = fmaf(x.x, w, acc.x);
            acc.y = fmaf(x.y, w, acc.y);
            acc.z = fmaf(x.z, w, acc.z);
            acc.w = fmaf(x.w, w, acc.w);
        }
        int rb = row0 + r4 * 4;
        out[(size_t)(rb + 0) * KDIM + k] = acc.x;
        out[(size_t)(rb + 1) * KDIM + k] = acc.y;
        out[(size_t)(rb + 2) * KDIM + k] = acc.z;
        out[(size_t)(rb + 3) * KDIM + k] = acc.w;
    }
}

// ---------------------------------------------------------------------------
extern "C" void kernel_launch(void* const* d_in, const int* in_sizes, int n_in,
                              void* d_out, int out_size) {
    const float* e1 = (const float*)d_in[0];
    const float* e2 = (const float*)d_in[1];
    const float* Wb = (const float*)d_in[2];
    const float* Wd = (const float*)d_in[3];
    const float* Wg = (const float*)d_in[4];
    const float* bg = (const float*)d_in[5];
    const float* bb = (const float*)d_in[6];
    const float* u  = (const float*)d_in[7];
    float* out = (float*)d_out;

    cudaFuncSetAttribute(proj_kernel, cudaFuncAttributeMaxDynamicSharedMemorySize, P_SMEM);
    cudaFuncSetAttribute(tmat_mma_kernel, cudaFuncAttributeMaxDynamicSharedMemorySize, MM_SMEM);
    cudaFuncSetAttribute(btp_mma_kernel, cudaFuncAttributeMaxDynamicSharedMemorySize, MM_SMEM);
    cudaFuncSetAttribute(gate_kernel, cudaFuncAttributeMaxDynamicSharedMemorySize, G_SMEM);

    convA_kernel<<<2 * ROWS1, KPAD>>>(e1, e2);
    convB_kernel<<<dim3(10, 10, KDIM), dim3(32, 8)>>>(Wb);
    proj_kernel<<<512, P_THREADS, P_SMEM>>>(e1, e2, Wd, Wg);
    tmat_mma_kernel<<<dim3(ROWS1 / 128, TROW / 128), MM_THREADS, MM_SMEM>>>();
    btp_mma_kernel<<<dim3(6400 / 128, 1, BDIM), MM_THREADS, MM_SMEM>>>();
    gate_kernel<<<ROWS1, 128, G_SMEM>>>(bg, bb, u, out);
}